// round 1
// baseline (speedup 1.0000x reference)
#include <cuda_runtime.h>
#include <cuda_bf16.h>

#define HID 128
#define NMAX 50000
#define EMAX 800000

// ---------------- scratch (static device globals; no allocation) ----------------
__device__ float g_bufA[(size_t)NMAX * HID];   // current h
__device__ float g_bufB[(size_t)NMAX * HID];   // hs = (h@W)*norm_src
__device__ float g_nsrc[NMAX];
__device__ float g_ndst[NMAX];
__device__ int   g_degout[NMAX];
__device__ int   g_degin[NMAX];
__device__ int   g_rowptr[NMAX + 1];
__device__ int   g_cursor[NMAX];
__device__ int   g_esrc[EMAX];
__device__ float g_loss;

// ---------------- prep kernels ----------------
__global__ void zero_kernel(int n) {
    int i = blockIdx.x * blockDim.x + threadIdx.x;
    if (i < n) { g_degout[i] = 0; g_degin[i] = 0; }
    if (i == 0) g_loss = 0.0f;
}

__global__ void count_deg_kernel(const int* __restrict__ src,
                                 const int* __restrict__ dst, int E) {
    int e = blockIdx.x * blockDim.x + threadIdx.x;
    if (e < E) {
        atomicAdd(&g_degout[src[e]], 1);
        atomicAdd(&g_degin[dst[e]], 1);
    }
}

__global__ void norm_kernel(int n) {
    int i = blockIdx.x * blockDim.x + threadIdx.x;
    if (i < n) {
        int od = g_degout[i]; if (od < 1) od = 1;
        int id = g_degin[i];  if (id < 1) id = 1;
        g_nsrc[i] = rsqrtf((float)od);
        g_ndst[i] = rsqrtf((float)id);
    }
}

// single-block exclusive scan of g_degin -> g_rowptr / g_cursor
__global__ void scan_kernel(int n) {
    __shared__ int wsum[32];
    int t = threadIdx.x, lane = t & 31, w = t >> 5;
    int carry = 0;
    for (int base = 0; base < n; base += 1024) {
        int idx = base + t;
        int v = (idx < n) ? g_degin[idx] : 0;
        int x = v;
        #pragma unroll
        for (int o = 1; o < 32; o <<= 1) {
            int y = __shfl_up_sync(0xffffffffu, x, o);
            if (lane >= o) x += y;
        }
        if (lane == 31) wsum[w] = x;
        __syncthreads();
        if (w == 0) {
            int s = wsum[lane];
            #pragma unroll
            for (int o = 1; o < 32; o <<= 1) {
                int y = __shfl_up_sync(0xffffffffu, s, o);
                if (lane >= o) s += y;
            }
            wsum[lane] = s;
        }
        __syncthreads();
        int woff = (w > 0) ? wsum[w - 1] : 0;
        int excl = carry + woff + x - v;
        if (idx < n) { g_rowptr[idx] = excl; g_cursor[idx] = excl; }
        carry += wsum[31];
        __syncthreads();
    }
    if (t == 0) g_rowptr[n] = carry;
}

__global__ void fill_kernel(const int* __restrict__ src,
                            const int* __restrict__ dst, int E) {
    int e = blockIdx.x * blockDim.x + threadIdx.x;
    if (e < E) {
        int p = atomicAdd(&g_cursor[dst[e]], 1);
        g_esrc[p] = src[e];
    }
}

__global__ void copy_attr_kernel(const float* __restrict__ attr, int n4) {
    int i = blockIdx.x * blockDim.x + threadIdx.x;
    if (i < n4) ((float4*)g_bufA)[i] = ((const float4*)attr)[i];
}

__global__ void mask_kernel(const int* __restrict__ mask_nodes,
                            const float* __restrict__ token, int nmask) {
    int w = (blockIdx.x * blockDim.x + threadIdx.x) >> 5;
    int lane = threadIdx.x & 31;
    if (w < nmask) {
        int node = mask_nodes[w];
        ((float4*)(g_bufA + (size_t)node * HID))[lane] = ((const float4*)token)[lane];
    }
}

// ---------------- GEMM: out = (h @ W) * norm_src (row scale) ----------------
// block: 64 rows x 128 cols, 256 threads, per-thread 8x4 tile.
__global__ __launch_bounds__(256) void gemm_scale_kernel(
    const float* __restrict__ h, const float* __restrict__ W,
    float* __restrict__ out, int nrows) {
    extern __shared__ float sh[];
    float* Wsh = sh;               // 128*128
    float* hsh = sh + HID * HID;   // 64*128
    int tid = threadIdx.x;

    for (int i = tid; i < HID * HID / 4; i += 256)
        ((float4*)Wsh)[i] = ((const float4*)W)[i];

    int row0 = blockIdx.x * 64;
    for (int i = tid; i < 64 * HID / 4; i += 256) {
        int r = i >> 5, c = i & 31;
        int gr = row0 + r;
        float4 v = make_float4(0.f, 0.f, 0.f, 0.f);
        if (gr < nrows) v = ((const float4*)(h + (size_t)gr * HID))[c];
        ((float4*)(hsh + r * HID))[c] = v;
    }
    __syncthreads();

    int trow = tid >> 5, tcol = tid & 31;
    float acc[8][4];
    #pragma unroll
    for (int i = 0; i < 8; i++)
        #pragma unroll
        for (int j = 0; j < 4; j++) acc[i][j] = 0.f;

    #pragma unroll 16
    for (int k = 0; k < HID; k++) {
        float4 b = ((const float4*)(Wsh + k * HID))[tcol];
        float a[8];
        #pragma unroll
        for (int i = 0; i < 8; i++) a[i] = hsh[(trow * 8 + i) * HID + k];
        #pragma unroll
        for (int i = 0; i < 8; i++) {
            acc[i][0] += a[i] * b.x;
            acc[i][1] += a[i] * b.y;
            acc[i][2] += a[i] * b.z;
            acc[i][3] += a[i] * b.w;
        }
    }

    #pragma unroll
    for (int i = 0; i < 8; i++) {
        int gr = row0 + trow * 8 + i;
        if (gr < nrows) {
            float s = g_nsrc[gr];
            float4 o = make_float4(acc[i][0] * s, acc[i][1] * s,
                                   acc[i][2] * s, acc[i][3] * s);
            ((float4*)(out + (size_t)gr * HID))[tcol] = o;
        }
    }
}

// ---------------- CSR aggregation + norm_dst + bias + relu ----------------
// one warp per node, lane handles a float4 (128 floats = 32 lanes * 4)
__global__ void aggregate_kernel(const float* __restrict__ hs,
                                 const float* __restrict__ bias,
                                 float* __restrict__ out, int n) {
    int w = (blockIdx.x * blockDim.x + threadIdx.x) >> 5;
    int lane = threadIdx.x & 31;
    if (w >= n) return;
    int beg = g_rowptr[w], end = g_rowptr[w + 1];
    float ax = 0.f, ay = 0.f, az = 0.f, aw = 0.f;
    int i = beg;
    for (; i + 2 <= end; i += 2) {
        int s0 = g_esrc[i], s1 = g_esrc[i + 1];
        float4 v0 = __ldg((const float4*)(hs + (size_t)s0 * HID) + lane);
        float4 v1 = __ldg((const float4*)(hs + (size_t)s1 * HID) + lane);
        ax += v0.x + v1.x; ay += v0.y + v1.y;
        az += v0.z + v1.z; aw += v0.w + v1.w;
    }
    if (i < end) {
        int s0 = g_esrc[i];
        float4 v0 = __ldg((const float4*)(hs + (size_t)s0 * HID) + lane);
        ax += v0.x; ay += v0.y; az += v0.z; aw += v0.w;
    }
    float nd = g_ndst[w];
    float4 b = __ldg((const float4*)bias + lane);
    float4 o;
    o.x = fmaxf(ax * nd + b.x, 0.f);
    o.y = fmaxf(ay * nd + b.y, 0.f);
    o.z = fmaxf(az * nd + b.z, 0.f);
    o.w = fmaxf(aw * nd + b.w, 0.f);
    ((float4*)(out + (size_t)w * HID))[lane] = o;
}

// ---------------- fused decoder GEMM (masked rows only) + MSE ----------------
__global__ __launch_bounds__(256) void decode_loss_kernel(
    const float* __restrict__ h, const float* __restrict__ dW,
    const float* __restrict__ db, const float* __restrict__ attr,
    const int* __restrict__ mask_nodes, int nmask) {
    extern __shared__ float sh[];
    float* Wsh = sh;
    float* hsh = sh + HID * HID;
    __shared__ int rows[64];
    __shared__ float wpart[8];
    int tid = threadIdx.x;

    for (int i = tid; i < HID * HID / 4; i += 256)
        ((float4*)Wsh)[i] = ((const float4*)dW)[i];

    int m0 = blockIdx.x * 64;
    if (tid < 64) {
        int mi = m0 + tid;
        rows[tid] = (mi < nmask) ? mask_nodes[mi] : -1;
    }
    __syncthreads();

    for (int i = tid; i < 64 * 32; i += 256) {
        int r = i >> 5, c = i & 31;
        int node = rows[r];
        float4 v = make_float4(0.f, 0.f, 0.f, 0.f);
        if (node >= 0) v = ((const float4*)(h + (size_t)node * HID))[c];
        ((float4*)(hsh + r * HID))[c] = v;
    }
    __syncthreads();

    int trow = tid >> 5, tcol = tid & 31;
    float acc[8][4];
    #pragma unroll
    for (int i = 0; i < 8; i++)
        #pragma unroll
        for (int j = 0; j < 4; j++) acc[i][j] = 0.f;

    #pragma unroll 16
    for (int k = 0; k < HID; k++) {
        float4 b = ((const float4*)(Wsh + k * HID))[tcol];
        float a[8];
        #pragma unroll
        for (int i = 0; i < 8; i++) a[i] = hsh[(trow * 8 + i) * HID + k];
        #pragma unroll
        for (int i = 0; i < 8; i++) {
            acc[i][0] += a[i] * b.x;
            acc[i][1] += a[i] * b.y;
            acc[i][2] += a[i] * b.z;
            acc[i][3] += a[i] * b.w;
        }
    }

    float4 b4 = __ldg((const float4*)db + tcol);
    float sse = 0.f;
    #pragma unroll
    for (int i = 0; i < 8; i++) {
        int node = rows[trow * 8 + i];
        if (node >= 0) {
            float4 a = __ldg((const float4*)(attr + (size_t)node * HID) + tcol);
            float d0 = acc[i][0] + b4.x - a.x;
            float d1 = acc[i][1] + b4.y - a.y;
            float d2 = acc[i][2] + b4.z - a.z;
            float d3 = acc[i][3] + b4.w - a.w;
            sse += d0 * d0 + d1 * d1 + d2 * d2 + d3 * d3;
        }
    }
    #pragma unroll
    for (int o = 16; o > 0; o >>= 1)
        sse += __shfl_down_sync(0xffffffffu, sse, o);
    if ((tid & 31) == 0) wpart[tid >> 5] = sse;
    __syncthreads();
    if (tid == 0) {
        float t = 0.f;
        #pragma unroll
        for (int i = 0; i < 8; i++) t += wpart[i];
        atomicAdd(&g_loss, t);
    }
}

__global__ void finalize_kernel(float* __restrict__ out, int nmask) {
    out[0] = g_loss / (float)((size_t)nmask * HID);
}

// ---------------- host launcher ----------------
extern "C" void kernel_launch(void* const* d_in, const int* in_sizes, int n_in,
                              void* d_out, int out_size) {
    const float* attr       = (const float*)d_in[0];
    const int*   src        = (const int*)d_in[1];
    const int*   dst        = (const int*)d_in[2];
    const float* Ws         = (const float*)d_in[3];
    const float* bs         = (const float*)d_in[4];
    const float* dec_W      = (const float*)d_in[5];
    const float* dec_b      = (const float*)d_in[6];
    const float* mask_token = (const float*)d_in[7];
    const int*   mask_nodes = (const int*)d_in[8];

    int N     = in_sizes[0] / HID;
    int E     = in_sizes[1];
    int nmask = in_sizes[8];

    float* bufA = nullptr;
    float* bufB = nullptr;
    cudaGetSymbolAddress((void**)&bufA, g_bufA);
    cudaGetSymbolAddress((void**)&bufB, g_bufB);

    const int smem = (HID * HID + 64 * HID) * (int)sizeof(float);  // 96 KB
    cudaFuncSetAttribute(gemm_scale_kernel,
                         cudaFuncAttributeMaxDynamicSharedMemorySize, smem);
    cudaFuncSetAttribute(decode_loss_kernel,
                         cudaFuncAttributeMaxDynamicSharedMemorySize, smem);

    zero_kernel<<<(N + 255) / 256, 256>>>(N);
    count_deg_kernel<<<(E + 255) / 256, 256>>>(src, dst, E);
    norm_kernel<<<(N + 255) / 256, 256>>>(N);
    scan_kernel<<<1, 1024>>>(N);
    fill_kernel<<<(E + 255) / 256, 256>>>(src, dst, E);
    copy_attr_kernel<<<(N * HID / 4 + 255) / 256, 256>>>(attr, N * HID / 4);
    mask_kernel<<<(nmask * 32 + 255) / 256, 256>>>(mask_nodes, mask_token, nmask);

    for (int l = 0; l < 3; l++) {
        gemm_scale_kernel<<<(N + 63) / 64, 256, smem>>>(
            bufA, Ws + (size_t)l * HID * HID, bufB, N);
        aggregate_kernel<<<(N * 32 + 255) / 256, 256>>>(
            bufB, bs + (size_t)l * HID, bufA, N);
    }

    decode_loss_kernel<<<(nmask + 63) / 64, 256, smem>>>(
        bufA, dec_W, dec_b, attr, mask_nodes, nmask);
    finalize_kernel<<<1, 1>>>((float*)d_out, nmask);
}

// round 2
// speedup vs baseline: 1.1473x; 1.1473x over previous
#include <cuda_runtime.h>
#include <cuda_bf16.h>

#define HID 128
#define NMAX 50000
#define EMAX 800000
#define SCAN_BLK 1024
#define NBLK_MAX 64

// ---------------- scratch (static device globals; no allocation) ----------------
__device__ float g_bufA[(size_t)NMAX * HID];   // current h
__device__ float g_bufB[(size_t)NMAX * HID];   // hs = (h@W)*norm_src
__device__ float g_nsrc[NMAX];
__device__ float g_ndst[NMAX];
__device__ int   g_degout[NMAX];
__device__ int   g_degin[NMAX];
__device__ int   g_rowptr[NMAX + 1];
__device__ int   g_cursor[NMAX];
__device__ int   g_esrc[EMAX];
__device__ int   g_bsum[NBLK_MAX];
__device__ int   g_boff[NBLK_MAX];
__device__ float g_loss;

// ---------------- packed fp32x2 FMA helpers (sm_103a) ----------------
__device__ __forceinline__ unsigned long long pack2(float lo, float hi) {
    unsigned long long r;
    asm("mov.b64 %0, {%1, %2};" : "=l"(r) : "f"(lo), "f"(hi));
    return r;
}
__device__ __forceinline__ void fma2(unsigned long long& d,
                                     unsigned long long a, unsigned long long b) {
    asm("fma.rn.f32x2 %0, %1, %2, %3;" : "=l"(d) : "l"(a), "l"(b), "l"(d));
}
__device__ __forceinline__ float2 unpack2(unsigned long long v) {
    float lo, hi;
    asm("mov.b64 {%0, %1}, %2;" : "=f"(lo), "=f"(hi) : "l"(v));
    return make_float2(lo, hi);
}

// ---------------- prep kernels ----------------
__global__ void zero_kernel(int n) {
    int i = blockIdx.x * blockDim.x + threadIdx.x;
    if (i < n) { g_degout[i] = 0; g_degin[i] = 0; }
    if (i == 0) g_loss = 0.0f;
}

__global__ void count_deg_kernel(const int* __restrict__ src,
                                 const int* __restrict__ dst, int E) {
    int e = blockIdx.x * blockDim.x + threadIdx.x;
    if (e < E) {
        atomicAdd(&g_degout[src[e]], 1);
        atomicAdd(&g_degin[dst[e]], 1);
    }
}

// phase 1: per-block exclusive scan of degin (local), block totals, fused norms
__global__ void scan1_kernel(int n) {
    __shared__ int wsum[32];
    int t = threadIdx.x, lane = t & 31, w = t >> 5;
    int idx = blockIdx.x * SCAN_BLK + t;
    int v = (idx < n) ? g_degin[idx] : 0;
    int x = v;
    #pragma unroll
    for (int o = 1; o < 32; o <<= 1) {
        int y = __shfl_up_sync(0xffffffffu, x, o);
        if (lane >= o) x += y;
    }
    if (lane == 31) wsum[w] = x;
    __syncthreads();
    if (w == 0) {
        int s = wsum[lane];
        #pragma unroll
        for (int o = 1; o < 32; o <<= 1) {
            int y = __shfl_up_sync(0xffffffffu, s, o);
            if (lane >= o) s += y;
        }
        wsum[lane] = s;
    }
    __syncthreads();
    int woff = (w > 0) ? wsum[w - 1] : 0;
    if (idx < n) g_rowptr[idx] = woff + x - v;   // block-local exclusive
    if (t == 0) g_bsum[blockIdx.x] = wsum[31];
    // fused norms
    if (idx < n) {
        int od = g_degout[idx]; if (od < 1) od = 1;
        int id = v;             if (id < 1) id = 1;
        g_nsrc[idx] = rsqrtf((float)od);
        g_ndst[idx] = rsqrtf((float)id);
    }
}

// phase 2: single block exclusive scan of block totals (nb <= 64)
__global__ void scan2_kernel(int nb) {
    __shared__ int wsum[32];
    int t = threadIdx.x, lane = t & 31, w = t >> 5;
    int v = (t < nb) ? g_bsum[t] : 0;
    int x = v;
    #pragma unroll
    for (int o = 1; o < 32; o <<= 1) {
        int y = __shfl_up_sync(0xffffffffu, x, o);
        if (lane >= o) x += y;
    }
    if (lane == 31) wsum[w] = x;
    __syncthreads();
    if (w == 0) {
        int s = wsum[lane];
        #pragma unroll
        for (int o = 1; o < 32; o <<= 1) {
            int y = __shfl_up_sync(0xffffffffu, s, o);
            if (lane >= o) s += y;
        }
        wsum[lane] = s;
    }
    __syncthreads();
    int woff = (w > 0) ? wsum[w - 1] : 0;
    if (t < nb) g_boff[t] = woff + x - v;
}

// phase 3: add block offsets, init cursor, set rowptr[n]
__global__ void scan3_kernel(int n, int E) {
    int idx = blockIdx.x * blockDim.x + threadIdx.x;
    if (idx < n) {
        int val = g_rowptr[idx] + g_boff[idx >> 10];
        g_rowptr[idx] = val;
        g_cursor[idx] = val;
    }
    if (idx == 0) g_rowptr[n] = E;
}

__global__ void fill_kernel(const int* __restrict__ src,
                            const int* __restrict__ dst, int E) {
    int e = blockIdx.x * blockDim.x + threadIdx.x;
    if (e < E) {
        int p = atomicAdd(&g_cursor[dst[e]], 1);
        g_esrc[p] = src[e];
    }
}

__global__ void copy_attr_kernel(const float* __restrict__ attr, int n4) {
    int i = blockIdx.x * blockDim.x + threadIdx.x;
    if (i < n4) ((float4*)g_bufA)[i] = ((const float4*)attr)[i];
}

__global__ void mask_kernel(const int* __restrict__ mask_nodes,
                            const float* __restrict__ token, int nmask) {
    int w = (blockIdx.x * blockDim.x + threadIdx.x) >> 5;
    int lane = threadIdx.x & 31;
    if (w < nmask) {
        int node = mask_nodes[w];
        ((float4*)(g_bufA + (size_t)node * HID))[lane] = ((const float4*)token)[lane];
    }
}

// ---------------- GEMM: out = (h @ W) * norm_src (row scale) ----------------
// block: 64 rows x 128 cols, 256 threads, per-thread 8x4 tile, f32x2 packed FMA
__global__ __launch_bounds__(256) void gemm_scale_kernel(
    const float* __restrict__ h, const float* __restrict__ W,
    float* __restrict__ out, int nrows) {
    extern __shared__ float sh[];
    float* Wsh = sh;               // 128*128
    float* hsh = sh + HID * HID;   // 64*128
    int tid = threadIdx.x;

    for (int i = tid; i < HID * HID / 4; i += 256)
        ((float4*)Wsh)[i] = ((const float4*)W)[i];

    int row0 = blockIdx.x * 64;
    for (int i = tid; i < 64 * HID / 4; i += 256) {
        int r = i >> 5, c = i & 31;
        int gr = row0 + r;
        float4 v = make_float4(0.f, 0.f, 0.f, 0.f);
        if (gr < nrows) v = ((const float4*)(h + (size_t)gr * HID))[c];
        ((float4*)(hsh + r * HID))[c] = v;
    }
    __syncthreads();

    int trow = tid >> 5, tcol = tid & 31;
    unsigned long long acc01[8], acc23[8];
    #pragma unroll
    for (int i = 0; i < 8; i++) { acc01[i] = 0ull; acc23[i] = 0ull; }

    #pragma unroll 2
    for (int k4 = 0; k4 < HID / 4; k4++) {
        float4 a4[8];
        #pragma unroll
        for (int i = 0; i < 8; i++)
            a4[i] = ((const float4*)(hsh + (trow * 8 + i) * HID))[k4];  // warp broadcast
        #pragma unroll
        for (int kk = 0; kk < 4; kk++) {
            float4 b = ((const float4*)(Wsh + (k4 * 4 + kk) * HID))[tcol];
            unsigned long long b01 = pack2(b.x, b.y);
            unsigned long long b23 = pack2(b.z, b.w);
            #pragma unroll
            for (int i = 0; i < 8; i++) {
                float av = (kk == 0) ? a4[i].x : (kk == 1) ? a4[i].y
                         : (kk == 2) ? a4[i].z : a4[i].w;
                unsigned long long a2 = pack2(av, av);
                fma2(acc01[i], a2, b01);
                fma2(acc23[i], a2, b23);
            }
        }
    }

    #pragma unroll
    for (int i = 0; i < 8; i++) {
        int gr = row0 + trow * 8 + i;
        if (gr < nrows) {
            float s = g_nsrc[gr];
            float2 p01 = unpack2(acc01[i]);
            float2 p23 = unpack2(acc23[i]);
            float4 o = make_float4(p01.x * s, p01.y * s, p23.x * s, p23.y * s);
            ((float4*)(out + (size_t)gr * HID))[tcol] = o;
        }
    }
}

// ---------------- CSR aggregation + norm_dst + bias + relu ----------------
__global__ void aggregate_kernel(const float* __restrict__ hs,
                                 const float* __restrict__ bias,
                                 float* __restrict__ out, int n) {
    int w = (blockIdx.x * blockDim.x + threadIdx.x) >> 5;
    int lane = threadIdx.x & 31;
    if (w >= n) return;
    int beg = g_rowptr[w], end = g_rowptr[w + 1];
    float ax = 0.f, ay = 0.f, az = 0.f, aw = 0.f;
    int i = beg;
    for (; i + 2 <= end; i += 2) {
        int s0 = g_esrc[i], s1 = g_esrc[i + 1];
        float4 v0 = __ldg((const float4*)(hs + (size_t)s0 * HID) + lane);
        float4 v1 = __ldg((const float4*)(hs + (size_t)s1 * HID) + lane);
        ax += v0.x + v1.x; ay += v0.y + v1.y;
        az += v0.z + v1.z; aw += v0.w + v1.w;
    }
    if (i < end) {
        int s0 = g_esrc[i];
        float4 v0 = __ldg((const float4*)(hs + (size_t)s0 * HID) + lane);
        ax += v0.x; ay += v0.y; az += v0.z; aw += v0.w;
    }
    float nd = g_ndst[w];
    float4 b = __ldg((const float4*)bias + lane);
    float4 o;
    o.x = fmaxf(ax * nd + b.x, 0.f);
    o.y = fmaxf(ay * nd + b.y, 0.f);
    o.z = fmaxf(az * nd + b.z, 0.f);
    o.w = fmaxf(aw * nd + b.w, 0.f);
    ((float4*)(out + (size_t)w * HID))[lane] = o;
}

// ---------------- fused decoder GEMM (masked rows only) + MSE ----------------
__global__ __launch_bounds__(256) void decode_loss_kernel(
    const float* __restrict__ h, const float* __restrict__ dW,
    const float* __restrict__ db, const float* __restrict__ attr,
    const int* __restrict__ mask_nodes, int nmask) {
    extern __shared__ float sh[];
    float* Wsh = sh;
    float* hsh = sh + HID * HID;
    __shared__ int rows[64];
    __shared__ float wpart[8];
    int tid = threadIdx.x;

    for (int i = tid; i < HID * HID / 4; i += 256)
        ((float4*)Wsh)[i] = ((const float4*)dW)[i];

    int m0 = blockIdx.x * 64;
    if (tid < 64) {
        int mi = m0 + tid;
        rows[tid] = (mi < nmask) ? mask_nodes[mi] : -1;
    }
    __syncthreads();

    for (int i = tid; i < 64 * 32; i += 256) {
        int r = i >> 5, c = i & 31;
        int node = rows[r];
        float4 v = make_float4(0.f, 0.f, 0.f, 0.f);
        if (node >= 0) v = ((const float4*)(h + (size_t)node * HID))[c];
        ((float4*)(hsh + r * HID))[c] = v;
    }
    __syncthreads();

    int trow = tid >> 5, tcol = tid & 31;
    unsigned long long acc01[8], acc23[8];
    #pragma unroll
    for (int i = 0; i < 8; i++) { acc01[i] = 0ull; acc23[i] = 0ull; }

    #pragma unroll 2
    for (int k4 = 0; k4 < HID / 4; k4++) {
        float4 a4[8];
        #pragma unroll
        for (int i = 0; i < 8; i++)
            a4[i] = ((const float4*)(hsh + (trow * 8 + i) * HID))[k4];
        #pragma unroll
        for (int kk = 0; kk < 4; kk++) {
            float4 b = ((const float4*)(Wsh + (k4 * 4 + kk) * HID))[tcol];
            unsigned long long b01 = pack2(b.x, b.y);
            unsigned long long b23 = pack2(b.z, b.w);
            #pragma unroll
            for (int i = 0; i < 8; i++) {
                float av = (kk == 0) ? a4[i].x : (kk == 1) ? a4[i].y
                         : (kk == 2) ? a4[i].z : a4[i].w;
                unsigned long long a2 = pack2(av, av);
                fma2(acc01[i], a2, b01);
                fma2(acc23[i], a2, b23);
            }
        }
    }

    float4 b4 = __ldg((const float4*)db + tcol);
    float sse = 0.f;
    #pragma unroll
    for (int i = 0; i < 8; i++) {
        int node = rows[trow * 8 + i];
        if (node >= 0) {
            float4 a = __ldg((const float4*)(attr + (size_t)node * HID) + tcol);
            float2 p01 = unpack2(acc01[i]);
            float2 p23 = unpack2(acc23[i]);
            float d0 = p01.x + b4.x - a.x;
            float d1 = p01.y + b4.y - a.y;
            float d2 = p23.x + b4.z - a.z;
            float d3 = p23.y + b4.w - a.w;
            sse += d0 * d0 + d1 * d1 + d2 * d2 + d3 * d3;
        }
    }
    #pragma unroll
    for (int o = 16; o > 0; o >>= 1)
        sse += __shfl_down_sync(0xffffffffu, sse, o);
    if ((tid & 31) == 0) wpart[tid >> 5] = sse;
    __syncthreads();
    if (tid == 0) {
        float t = 0.f;
        #pragma unroll
        for (int i = 0; i < 8; i++) t += wpart[i];
        atomicAdd(&g_loss, t);
    }
}

__global__ void finalize_kernel(float* __restrict__ out, int nmask) {
    out[0] = g_loss / (float)((size_t)nmask * HID);
}

// ---------------- host launcher ----------------
extern "C" void kernel_launch(void* const* d_in, const int* in_sizes, int n_in,
                              void* d_out, int out_size) {
    const float* attr       = (const float*)d_in[0];
    const int*   src        = (const int*)d_in[1];
    const int*   dst        = (const int*)d_in[2];
    const float* Ws         = (const float*)d_in[3];
    const float* bs         = (const float*)d_in[4];
    const float* dec_W      = (const float*)d_in[5];
    const float* dec_b      = (const float*)d_in[6];
    const float* mask_token = (const float*)d_in[7];
    const int*   mask_nodes = (const int*)d_in[8];

    int N     = in_sizes[0] / HID;
    int E     = in_sizes[1];
    int nmask = in_sizes[8];
    int nb    = (N + SCAN_BLK - 1) / SCAN_BLK;

    float* bufA = nullptr;
    float* bufB = nullptr;
    cudaGetSymbolAddress((void**)&bufA, g_bufA);
    cudaGetSymbolAddress((void**)&bufB, g_bufB);

    const int smem = (HID * HID + 64 * HID) * (int)sizeof(float);  // 96 KB
    cudaFuncSetAttribute(gemm_scale_kernel,
                         cudaFuncAttributeMaxDynamicSharedMemorySize, smem);
    cudaFuncSetAttribute(decode_loss_kernel,
                         cudaFuncAttributeMaxDynamicSharedMemorySize, smem);

    zero_kernel<<<(N + 255) / 256, 256>>>(N);
    count_deg_kernel<<<(E + 255) / 256, 256>>>(src, dst, E);
    scan1_kernel<<<nb, SCAN_BLK>>>(N);
    scan2_kernel<<<1, SCAN_BLK>>>(nb);
    scan3_kernel<<<(N + 255) / 256, 256>>>(N, E);
    fill_kernel<<<(E + 255) / 256, 256>>>(src, dst, E);
    copy_attr_kernel<<<(N * HID / 4 + 255) / 256, 256>>>(attr, N * HID / 4);
    mask_kernel<<<(nmask * 32 + 255) / 256, 256>>>(mask_nodes, mask_token, nmask);

    for (int l = 0; l < 3; l++) {
        gemm_scale_kernel<<<(N + 63) / 64, 256, smem>>>(
            bufA, Ws + (size_t)l * HID * HID, bufB, N);
        aggregate_kernel<<<(N * 32 + 255) / 256, 256>>>(
            bufB, bs + (size_t)l * HID, bufA, N);
    }

    decode_loss_kernel<<<(nmask + 63) / 64, 256, smem>>>(
        bufA, dec_W, dec_b, attr, mask_nodes, nmask);
    finalize_kernel<<<1, 1>>>((float*)d_out, nmask);
}

// round 6
// speedup vs baseline: 1.3509x; 1.1775x over previous
#include <cuda_runtime.h>
#include <cuda_bf16.h>
#include <cstdint>

#define HID 128
#define NMAX 50000
#define NPADMAX 50048           // ceil(50000/128)*128
#define EMAX 800000
#define SCAN_BLK 1024
#define NBLK_MAX 64
#define TILE_ELEMS 16384        // 128x128
#define ASTRIDE 136             // smem row stride in bf16 elems (272B: conflict-free ldmatrix)

// ---------------- scratch (static device globals; no allocation) ----------------
__device__ float         g_bufA[(size_t)NMAX * HID];        // layer-3 output (fp32, decoder input)
__device__ float         g_hs[(size_t)NPADMAX * HID];       // GEMM output (fp32, aggregation input)
__device__ __nv_bfloat16 g_hHi[(size_t)NPADMAX * HID];      // h hi part (GEMM A)
__device__ __nv_bfloat16 g_hLo[(size_t)NPADMAX * HID];      // h lo part
__device__ __nv_bfloat16 g_WHi[3 * TILE_ELEMS];             // W hi, row-major [l][k][n]
__device__ __nv_bfloat16 g_WLo[3 * TILE_ELEMS];             // W lo
__device__ float g_nsrc[NPADMAX];
__device__ float g_ndst[NMAX];
__device__ int   g_degout[NMAX];
__device__ int   g_degin[NMAX];
__device__ int   g_rowptr[NMAX + 1];
__device__ int   g_cursor[NMAX];
__device__ int   g_esrc[EMAX];
__device__ int   g_bsum[NBLK_MAX];
__device__ int   g_boff[NBLK_MAX];
__device__ float g_loss;

// ---------------- helpers ----------------
__device__ __forceinline__ uint32_t smem_u32(const void* p) {
    uint32_t a;
    asm("{ .reg .u64 t; cvta.to.shared.u64 t, %1; cvt.u32.u64 %0, t; }" : "=r"(a) : "l"(p));
    return a;
}
__device__ __forceinline__ unsigned long long pack2(float lo, float hi) {
    unsigned long long r;
    asm("mov.b64 %0, {%1, %2};" : "=l"(r) : "f"(lo), "f"(hi));
    return r;
}
__device__ __forceinline__ void fma2(unsigned long long& d,
                                     unsigned long long a, unsigned long long b) {
    asm("fma.rn.f32x2 %0, %1, %2, %3;" : "=l"(d) : "l"(a), "l"(b), "l"(d));
}
__device__ __forceinline__ float2 unpack2(unsigned long long v) {
    float lo, hi;
    asm("mov.b64 {%0, %1}, %2;" : "=f"(lo), "=f"(hi) : "l"(v));
    return make_float2(lo, hi);
}
// bf16x2 pack: first arg -> low half
__device__ __forceinline__ uint32_t bf16x2(float lo, float hi) {
    uint32_t r;
    asm("cvt.rn.bf16x2.f32 %0, %1, %2;" : "=r"(r) : "f"(hi), "f"(lo));
    return r;
}
// split x into hi/lo bf16 parts, packed for two consecutive values
__device__ __forceinline__ void split2(float x, float y, uint32_t& hi, uint32_t& lo) {
    __nv_bfloat16 xh = __float2bfloat16(x), yh = __float2bfloat16(y);
    float xr = x - __bfloat162float(xh), yr = y - __bfloat162float(yh);
    hi = bf16x2(__bfloat162float(xh), __bfloat162float(yh));
    lo = bf16x2(xr, yr);
}

// ---------------- prep kernels ----------------
__global__ void zero_kernel(int n) {
    int i = blockIdx.x * blockDim.x + threadIdx.x;
    if (i < n) { g_degout[i] = 0; g_degin[i] = 0; }
    if (i == 0) g_loss = 0.0f;
}

__global__ void count_deg_kernel(const int* __restrict__ src,
                                 const int* __restrict__ dst, int E) {
    int e = blockIdx.x * blockDim.x + threadIdx.x;
    if (e < E) {
        atomicAdd(&g_degout[src[e]], 1);
        atomicAdd(&g_degin[dst[e]], 1);
    }
}

__global__ void scan1_kernel(int n, int npad) {
    __shared__ int wsum[32];
    int t = threadIdx.x, lane = t & 31, w = t >> 5;
    int idx = blockIdx.x * SCAN_BLK + t;
    int v = (idx < n) ? g_degin[idx] : 0;
    int x = v;
    #pragma unroll
    for (int o = 1; o < 32; o <<= 1) {
        int y = __shfl_up_sync(0xffffffffu, x, o);
        if (lane >= o) x += y;
    }
    if (lane == 31) wsum[w] = x;
    __syncthreads();
    if (w == 0) {
        int s = wsum[lane];
        #pragma unroll
        for (int o = 1; o < 32; o <<= 1) {
            int y = __shfl_up_sync(0xffffffffu, s, o);
            if (lane >= o) s += y;
        }
        wsum[lane] = s;
    }
    __syncthreads();
    int woff = (w > 0) ? wsum[w - 1] : 0;
    if (idx < n) g_rowptr[idx] = woff + x - v;
    if (t == 0) g_bsum[blockIdx.x] = wsum[31];
    if (idx < n) {
        int od = g_degout[idx]; if (od < 1) od = 1;
        int id = v;             if (id < 1) id = 1;
        g_nsrc[idx] = rsqrtf((float)od);
        g_ndst[idx] = rsqrtf((float)id);
    } else if (idx < npad) {
        g_nsrc[idx] = 0.0f;   // pad rows produce clean zeros
    }
}

__global__ void scan2_kernel(int nb) {
    __shared__ int wsum[32];
    int t = threadIdx.x, lane = t & 31, w = t >> 5;
    int v = (t < nb) ? g_bsum[t] : 0;
    int x = v;
    #pragma unroll
    for (int o = 1; o < 32; o <<= 1) {
        int y = __shfl_up_sync(0xffffffffu, x, o);
        if (lane >= o) x += y;
    }
    if (lane == 31) wsum[w] = x;
    __syncthreads();
    if (w == 0) {
        int s = wsum[lane];
        #pragma unroll
        for (int o = 1; o < 32; o <<= 1) {
            int y = __shfl_up_sync(0xffffffffu, s, o);
            if (lane >= o) s += y;
        }
        wsum[lane] = s;
    }
    __syncthreads();
    int woff = (w > 0) ? wsum[w - 1] : 0;
    if (t < nb) g_boff[t] = woff + x - v;
}

__global__ void scan3_kernel(int n, int E) {
    int idx = blockIdx.x * blockDim.x + threadIdx.x;
    if (idx < n) {
        int val = g_rowptr[idx] + g_boff[idx >> 10];
        g_rowptr[idx] = val;
        g_cursor[idx] = val;
    }
    if (idx == 0) g_rowptr[n] = E;
}

__global__ void fill_kernel(const int* __restrict__ src,
                            const int* __restrict__ dst, int E) {
    int e = blockIdx.x * blockDim.x + threadIdx.x;
    if (e < E) {
        int p = atomicAdd(&g_cursor[dst[e]], 1);
        g_esrc[p] = src[e];
    }
}

// W (3 layers fp32 [k][n]) -> hi/lo bf16 pairs, same layout
__global__ void convw_kernel(const float* __restrict__ Ws) {
    int i = blockIdx.x * blockDim.x + threadIdx.x;
    if (i < 3 * TILE_ELEMS / 2) {
        float2 v = ((const float2*)Ws)[i];
        uint32_t hi, lo;
        split2(v.x, v.y, hi, lo);
        ((uint32_t*)g_WHi)[i] = hi;
        ((uint32_t*)g_WLo)[i] = lo;
    }
}

// attr fp32 -> hi/lo bf16 (pad rows zeroed); one warp per row
__global__ void copy_attr_kernel(const float* __restrict__ attr, int n, int npad) {
    int node = (blockIdx.x * blockDim.x + threadIdx.x) >> 5;
    int lane = threadIdx.x & 31;
    if (node >= npad) return;
    float4 v = make_float4(0.f, 0.f, 0.f, 0.f);
    if (node < n) v = ((const float4*)(attr + (size_t)node * HID))[lane];
    uint32_t h0, l0, h1, l1;
    split2(v.x, v.y, h0, l0);
    split2(v.z, v.w, h1, l1);
    ((uint2*)(g_hHi + (size_t)node * HID))[lane] = make_uint2(h0, h1);
    ((uint2*)(g_hLo + (size_t)node * HID))[lane] = make_uint2(l0, l1);
}

__global__ void mask_kernel(const int* __restrict__ mask_nodes,
                            const float* __restrict__ token, int nmask) {
    int w = (blockIdx.x * blockDim.x + threadIdx.x) >> 5;
    int lane = threadIdx.x & 31;
    if (w >= nmask) return;
    int node = mask_nodes[w];
    float4 v = ((const float4*)token)[lane];
    uint32_t h0, l0, h1, l1;
    split2(v.x, v.y, h0, l0);
    split2(v.z, v.w, h1, l1);
    ((uint2*)(g_hHi + (size_t)node * HID))[lane] = make_uint2(h0, h1);
    ((uint2*)(g_hLo + (size_t)node * HID))[lane] = make_uint2(l0, l1);
}

// ---------------- split-bf16 HMMA GEMM: hs[tile] = (h_tile @ W) * nsrc ----------------
// 256 threads = 8 warps; warp w -> rows 16w..16w+15 x 128 cols.
// acc += Ahi*Bhi + Ahi*Blo + Alo*Bhi   (fp32 accumulate; ~1e-5 relative accuracy)
__global__ __launch_bounds__(256) void gemm_mma_kernel(
    const __nv_bfloat16* __restrict__ WHi, const __nv_bfloat16* __restrict__ WLo) {
    extern __shared__ __nv_bfloat16 sm[];
    __nv_bfloat16* sAh = sm;                     // 128 x ASTRIDE
    __nv_bfloat16* sAl = sm + 128 * ASTRIDE;
    __nv_bfloat16* sBh = sm + 2 * 128 * ASTRIDE;
    __nv_bfloat16* sBl = sm + 3 * 128 * ASTRIDE;
    int tid = threadIdx.x, lane = tid & 31, wid = tid >> 5;

    // load tiles: each thread owns one half-row = 64 bf16 = 128 bytes = 8 uint4 per buffer
    {
        int row = tid >> 1, half = tid & 1;
        size_t goff = (size_t)blockIdx.x * 128 * HID + row * HID + half * 64;
        const uint4* gah = (const uint4*)(g_hHi + goff);
        const uint4* gal = (const uint4*)(g_hLo + goff);
        const uint4* gbh = (const uint4*)(WHi + row * HID + half * 64);
        const uint4* gbl = (const uint4*)(WLo + row * HID + half * 64);
        uint4* pah = (uint4*)(sAh + row * ASTRIDE + half * 64);
        uint4* pal = (uint4*)(sAl + row * ASTRIDE + half * 64);
        uint4* pbh = (uint4*)(sBh + row * ASTRIDE + half * 64);
        uint4* pbl = (uint4*)(sBl + row * ASTRIDE + half * 64);
        #pragma unroll
        for (int i = 0; i < 8; i++) {          // FIX (was 4): full 128B half-row
            pah[i] = gah[i]; pal[i] = gal[i];
            pbh[i] = gbh[i]; pbl[i] = gbl[i];
        }
    }
    __syncthreads();

    uint32_t aoff = (uint32_t)(((wid * 16) + ((lane >> 3) & 1) * 8 + (lane & 7)) * ASTRIDE
                               + ((lane >> 4) * 8)) * 2;
    uint32_t boff = (uint32_t)((lane & 15) * ASTRIDE) * 2;
    uint32_t aHi = smem_u32(sAh) + aoff, aLo = smem_u32(sAl) + aoff;
    uint32_t bHi = smem_u32(sBh) + boff, bLo = smem_u32(sBl) + boff;

    float acc[16][4];
    #pragma unroll
    for (int j = 0; j < 16; j++)
        #pragma unroll
        for (int q = 0; q < 4; q++) acc[j][q] = 0.f;

    #pragma unroll
    for (int ks = 0; ks < 8; ks++) {
        uint32_t ah0, ah1, ah2, ah3, al0, al1, al2, al3;
        asm volatile("ldmatrix.sync.aligned.m8n8.x4.shared.b16 {%0,%1,%2,%3}, [%4];"
            : "=r"(ah0), "=r"(ah1), "=r"(ah2), "=r"(ah3) : "r"(aHi + ks * 32));
        asm volatile("ldmatrix.sync.aligned.m8n8.x4.shared.b16 {%0,%1,%2,%3}, [%4];"
            : "=r"(al0), "=r"(al1), "=r"(al2), "=r"(al3) : "r"(aLo + ks * 32));
        #pragma unroll
        for (int j = 0; j < 16; j++) {
            uint32_t off = (uint32_t)(ks * 16 * ASTRIDE + j * 8) * 2;
            uint32_t bh0, bh1, bl0, bl1;
            asm volatile("ldmatrix.sync.aligned.m8n8.x2.trans.shared.b16 {%0,%1}, [%2];"
                : "=r"(bh0), "=r"(bh1) : "r"(bHi + off));
            asm volatile("ldmatrix.sync.aligned.m8n8.x2.trans.shared.b16 {%0,%1}, [%2];"
                : "=r"(bl0), "=r"(bl1) : "r"(bLo + off));
            asm volatile(
                "mma.sync.aligned.m16n8k16.row.col.f32.bf16.bf16.f32 "
                "{%0,%1,%2,%3}, {%4,%5,%6,%7}, {%8,%9}, {%0,%1,%2,%3};"
                : "+f"(acc[j][0]), "+f"(acc[j][1]), "+f"(acc[j][2]), "+f"(acc[j][3])
                : "r"(ah0), "r"(ah1), "r"(ah2), "r"(ah3), "r"(bh0), "r"(bh1));
            asm volatile(
                "mma.sync.aligned.m16n8k16.row.col.f32.bf16.bf16.f32 "
                "{%0,%1,%2,%3}, {%4,%5,%6,%7}, {%8,%9}, {%0,%1,%2,%3};"
                : "+f"(acc[j][0]), "+f"(acc[j][1]), "+f"(acc[j][2]), "+f"(acc[j][3])
                : "r"(ah0), "r"(ah1), "r"(ah2), "r"(ah3), "r"(bl0), "r"(bl1));
            asm volatile(
                "mma.sync.aligned.m16n8k16.row.col.f32.bf16.bf16.f32 "
                "{%0,%1,%2,%3}, {%4,%5,%6,%7}, {%8,%9}, {%0,%1,%2,%3};"
                : "+f"(acc[j][0]), "+f"(acc[j][1]), "+f"(acc[j][2]), "+f"(acc[j][3])
                : "r"(al0), "r"(al1), "r"(al2), "r"(al3), "r"(bh0), "r"(bh1));
        }
    }

    // epilogue: scale by nsrc, store fp32 row-major
    int r0 = blockIdx.x * 128 + wid * 16 + (lane >> 2);
    int r1 = r0 + 8;
    float s0 = g_nsrc[r0], s1 = g_nsrc[r1];
    float2* o0 = (float2*)(g_hs + (size_t)r0 * HID) + (lane & 3);
    float2* o1 = (float2*)(g_hs + (size_t)r1 * HID) + (lane & 3);
    #pragma unroll
    for (int j = 0; j < 16; j++) {
        o0[j * 4] = make_float2(acc[j][0] * s0, acc[j][1] * s0);
        o1[j * 4] = make_float2(acc[j][2] * s1, acc[j][3] * s1);
    }
}

// ---------------- CSR aggregation (fp32 in) + norm_dst + bias + relu ----------------
// mode 0: write hi/lo bf16 to g_hHi/g_hLo; mode 1: write fp32 to g_bufA (decoder)
__global__ void aggregate_kernel(const float* __restrict__ bias, int n, int mode) {
    int w = (blockIdx.x * blockDim.x + threadIdx.x) >> 5;
    int lane = threadIdx.x & 31;
    if (w >= n) return;
    int beg = g_rowptr[w], end = g_rowptr[w + 1];
    float ax = 0.f, ay = 0.f, az = 0.f, aw = 0.f;
    int i = beg;
    for (; i + 2 <= end; i += 2) {
        int s0 = g_esrc[i], s1 = g_esrc[i + 1];
        float4 v0 = __ldg((const float4*)(g_hs + ((size_t)s0 << 7)) + lane);
        float4 v1 = __ldg((const float4*)(g_hs + ((size_t)s1 << 7)) + lane);
        ax += v0.x + v1.x; ay += v0.y + v1.y;
        az += v0.z + v1.z; aw += v0.w + v1.w;
    }
    if (i < end) {
        int s0 = g_esrc[i];
        float4 v0 = __ldg((const float4*)(g_hs + ((size_t)s0 << 7)) + lane);
        ax += v0.x; ay += v0.y; az += v0.z; aw += v0.w;
    }
    float nd = g_ndst[w];
    float4 b = __ldg((const float4*)bias + lane);
    float4 o;
    o.x = fmaxf(ax * nd + b.x, 0.f);
    o.y = fmaxf(ay * nd + b.y, 0.f);
    o.z = fmaxf(az * nd + b.z, 0.f);
    o.w = fmaxf(aw * nd + b.w, 0.f);
    if (mode == 0) {
        uint32_t h0, l0, h1, l1;
        split2(o.x, o.y, h0, l0);
        split2(o.z, o.w, h1, l1);
        ((uint2*)(g_hHi + (size_t)w * HID))[lane] = make_uint2(h0, h1);
        ((uint2*)(g_hLo + (size_t)w * HID))[lane] = make_uint2(l0, l1);
    } else {
        ((float4*)(g_bufA + (size_t)w * HID))[lane] = o;
    }
}

// ---------------- fused decoder GEMM (masked rows only) + MSE ----------------
__global__ __launch_bounds__(256) void decode_loss_kernel(
    const float* __restrict__ h, const float* __restrict__ dW,
    const float* __restrict__ db, const float* __restrict__ attr,
    const int* __restrict__ mask_nodes, int nmask) {
    extern __shared__ float sh[];
    float* Wsh = sh;
    float* hsh = sh + HID * HID;
    __shared__ int rows[64];
    __shared__ float wpart[8];
    int tid = threadIdx.x;

    for (int i = tid; i < HID * HID / 4; i += 256)
        ((float4*)Wsh)[i] = ((const float4*)dW)[i];

    int m0 = blockIdx.x * 64;
    if (tid < 64) {
        int mi = m0 + tid;
        rows[tid] = (mi < nmask) ? mask_nodes[mi] : -1;
    }
    __syncthreads();

    for (int i = tid; i < 64 * 32; i += 256) {
        int r = i >> 5, c = i & 31;
        int node = rows[r];
        float4 v = make_float4(0.f, 0.f, 0.f, 0.f);
        if (node >= 0) v = ((const float4*)(h + (size_t)node * HID))[c];
        ((float4*)(hsh + r * HID))[c] = v;
    }
    __syncthreads();

    int trow = tid >> 5, tcol = tid & 31;
    unsigned long long acc01[8], acc23[8];
    #pragma unroll
    for (int i = 0; i < 8; i++) { acc01[i] = 0ull; acc23[i] = 0ull; }

    #pragma unroll 2
    for (int k4 = 0; k4 < HID / 4; k4++) {
        float4 a4[8];
        #pragma unroll
        for (int i = 0; i < 8; i++)
            a4[i] = ((const float4*)(hsh + (trow * 8 + i) * HID))[k4];
        #pragma unroll
        for (int kk = 0; kk < 4; kk++) {
            float4 b = ((const float4*)(Wsh + (k4 * 4 + kk) * HID))[tcol];
            unsigned long long b01 = pack2(b.x, b.y);
            unsigned long long b23 = pack2(b.z, b.w);
            #pragma unroll
            for (int i = 0; i < 8; i++) {
                float av = (kk == 0) ? a4[i].x : (kk == 1) ? a4[i].y
                         : (kk == 2) ? a4[i].z : a4[i].w;
                unsigned long long a2 = pack2(av, av);
                fma2(acc01[i], a2, b01);
                fma2(acc23[i], a2, b23);
            }
        }
    }

    float4 b4 = __ldg((const float4*)db + tcol);
    float sse = 0.f;
    #pragma unroll
    for (int i = 0; i < 8; i++) {
        int node = rows[trow * 8 + i];
        if (node >= 0) {
            float4 a = __ldg((const float4*)(attr + (size_t)node * HID) + tcol);
            float2 p01 = unpack2(acc01[i]);
            float2 p23 = unpack2(acc23[i]);
            float d0 = p01.x + b4.x - a.x;
            float d1 = p01.y + b4.y - a.y;
            float d2 = p23.x + b4.z - a.z;
            float d3 = p23.y + b4.w - a.w;
            sse += d0 * d0 + d1 * d1 + d2 * d2 + d3 * d3;
        }
    }
    #pragma unroll
    for (int o = 16; o > 0; o >>= 1)
        sse += __shfl_down_sync(0xffffffffu, sse, o);
    if ((tid & 31) == 0) wpart[tid >> 5] = sse;
    __syncthreads();
    if (tid == 0) {
        float t = 0.f;
        #pragma unroll
        for (int i = 0; i < 8; i++) t += wpart[i];
        atomicAdd(&g_loss, t);
    }
}

__global__ void finalize_kernel(float* __restrict__ out, int nmask) {
    out[0] = g_loss / (float)((size_t)nmask * HID);
}

// ---------------- host launcher ----------------
extern "C" void kernel_launch(void* const* d_in, const int* in_sizes, int n_in,
                              void* d_out, int out_size) {
    const float* attr       = (const float*)d_in[0];
    const int*   src        = (const int*)d_in[1];
    const int*   dst        = (const int*)d_in[2];
    const float* Ws         = (const float*)d_in[3];
    const float* bs         = (const float*)d_in[4];
    const float* dec_W      = (const float*)d_in[5];
    const float* dec_b      = (const float*)d_in[6];
    const float* mask_token = (const float*)d_in[7];
    const int*   mask_nodes = (const int*)d_in[8];

    int N      = in_sizes[0] / HID;
    int E      = in_sizes[1];
    int nmask  = in_sizes[8];
    int npad   = (N + 127) & ~127;
    int ntiles = npad / 128;
    int nb     = (N + SCAN_BLK - 1) / SCAN_BLK;

    float* bufA = nullptr;
    __nv_bfloat16* WHi = nullptr;
    __nv_bfloat16* WLo = nullptr;
    cudaGetSymbolAddress((void**)&bufA, g_bufA);
    cudaGetSymbolAddress((void**)&WHi, g_WHi);
    cudaGetSymbolAddress((void**)&WLo, g_WLo);

    const int smem_gemm = 4 * 128 * ASTRIDE * 2;                        // 139264 B
    const int smem_dec  = (HID * HID + 64 * HID) * (int)sizeof(float);  // 96 KB
    cudaFuncSetAttribute(gemm_mma_kernel,
                         cudaFuncAttributeMaxDynamicSharedMemorySize, smem_gemm);
    cudaFuncSetAttribute(decode_loss_kernel,
                         cudaFuncAttributeMaxDynamicSharedMemorySize, smem_dec);

    zero_kernel<<<(N + 255) / 256, 256>>>(N);
    count_deg_kernel<<<(E + 255) / 256, 256>>>(src, dst, E);
    scan1_kernel<<<nb, SCAN_BLK>>>(N, npad);
    scan2_kernel<<<1, SCAN_BLK>>>(nb);
    scan3_kernel<<<(N + 255) / 256, 256>>>(N, E);
    fill_kernel<<<(E + 255) / 256, 256>>>(src, dst, E);
    convw_kernel<<<(3 * TILE_ELEMS / 2 + 255) / 256, 256>>>(Ws);
    copy_attr_kernel<<<(npad * 32 + 255) / 256, 256>>>(attr, N, npad);
    mask_kernel<<<(nmask * 32 + 255) / 256, 256>>>(mask_nodes, mask_token, nmask);

    for (int l = 0; l < 3; l++) {
        gemm_mma_kernel<<<ntiles, 256, smem_gemm>>>(
            WHi + (size_t)l * TILE_ELEMS, WLo + (size_t)l * TILE_ELEMS);
        aggregate_kernel<<<(N * 32 + 255) / 256, 256>>>(
            bs + (size_t)l * HID, N, (l == 2) ? 1 : 0);
    }

    decode_loss_kernel<<<(nmask + 63) / 64, 256, smem_dec>>>(
        bufA, dec_W, dec_b, attr, mask_nodes, nmask);
    finalize_kernel<<<1, 1>>>((float*)d_out, nmask);
}

// round 7
// speedup vs baseline: 1.6776x; 1.2419x over previous
#include <cuda_runtime.h>
#include <cuda_bf16.h>
#include <cstdint>

#define HID 128
#define NMAX 50000
#define NPADMAX 50048           // ceil(50000/128)*128
#define EMAX 800000
#define SCAN_BLK 1024
#define NBLK_MAX 64
#define TILE_ELEMS 16384        // 128x128
#define ASTRIDE 136             // smem row stride in bf16 elems (272B: conflict-free ldmatrix)

// ---------------- scratch (static device globals; no allocation) ----------------
__device__ float         g_bufA[(size_t)NMAX * HID];        // layer-3 output (fp32, decoder input)
__device__ __nv_bfloat16 g_hB[(size_t)NPADMAX * HID];       // h (bf16 row-major, GEMM A)
__device__ __nv_bfloat16 g_hs[(size_t)NPADMAX * HID];       // GEMM output (bf16 row-major)
__device__ __nv_bfloat16 g_Wb[3 * TILE_ELEMS];              // W bf16 row-major [l][k][n]
__device__ float g_nsrc[NPADMAX];
__device__ float g_ndst[NMAX];
__device__ int   g_degout[NMAX];
__device__ int   g_degin[NMAX];
__device__ int   g_rowptr[NMAX + 1];
__device__ int   g_cursor[NMAX];
__device__ int   g_esrc[EMAX];
__device__ int   g_bsum[NBLK_MAX];
__device__ float g_loss;

// ---------------- helpers ----------------
__device__ __forceinline__ uint32_t smem_u32(const void* p) {
    uint32_t a;
    asm("{ .reg .u64 t; cvta.to.shared.u64 t, %1; cvt.u32.u64 %0, t; }" : "=r"(a) : "l"(p));
    return a;
}
__device__ __forceinline__ unsigned long long pack2(float lo, float hi) {
    unsigned long long r;
    asm("mov.b64 %0, {%1, %2};" : "=l"(r) : "f"(lo), "f"(hi));
    return r;
}
__device__ __forceinline__ void fma2(unsigned long long& d,
                                     unsigned long long a, unsigned long long b) {
    asm("fma.rn.f32x2 %0, %1, %2, %3;" : "=l"(d) : "l"(a), "l"(b), "l"(d));
}
__device__ __forceinline__ float2 unpack2(unsigned long long v) {
    float lo, hi;
    asm("mov.b64 {%0, %1}, %2;" : "=f"(lo), "=f"(hi) : "l"(v));
    return make_float2(lo, hi);
}
// bf16x2 pack: first arg -> low half
__device__ __forceinline__ uint32_t bf16x2(float lo, float hi) {
    uint32_t r;
    asm("cvt.rn.bf16x2.f32 %0, %1, %2;" : "=r"(r) : "f"(hi), "f"(lo));
    return r;
}

// ---------------- prep kernels ----------------
__global__ void zero_kernel(int n) {
    int i = blockIdx.x * blockDim.x + threadIdx.x;
    if (i < n) { g_degout[i] = 0; g_degin[i] = 0; }
    if (i == 0) g_loss = 0.0f;
}

__global__ void count_deg_kernel(const int* __restrict__ src,
                                 const int* __restrict__ dst, int E) {
    int e = blockIdx.x * blockDim.x + threadIdx.x;
    if (e < E) {
        atomicAdd(&g_degout[src[e]], 1);
        atomicAdd(&g_degin[dst[e]], 1);
    }
}

// phase 1: per-block exclusive scan of degin (local), block totals, fused norms
__global__ void scan1_kernel(int n, int npad) {
    __shared__ int wsum[32];
    int t = threadIdx.x, lane = t & 31, w = t >> 5;
    int idx = blockIdx.x * SCAN_BLK + t;
    int v = (idx < n) ? g_degin[idx] : 0;
    int x = v;
    #pragma unroll
    for (int o = 1; o < 32; o <<= 1) {
        int y = __shfl_up_sync(0xffffffffu, x, o);
        if (lane >= o) x += y;
    }
    if (lane == 31) wsum[w] = x;
    __syncthreads();
    if (w == 0) {
        int s = wsum[lane];
        #pragma unroll
        for (int o = 1; o < 32; o <<= 1) {
            int y = __shfl_up_sync(0xffffffffu, s, o);
            if (lane >= o) s += y;
        }
        wsum[lane] = s;
    }
    __syncthreads();
    int woff = (w > 0) ? wsum[w - 1] : 0;
    if (idx < n) g_rowptr[idx] = woff + x - v;
    if (t == 0) g_bsum[blockIdx.x] = wsum[31];
    if (idx < n) {
        int od = g_degout[idx]; if (od < 1) od = 1;
        int id = v;             if (id < 1) id = 1;
        g_nsrc[idx] = rsqrtf((float)od);
        g_ndst[idx] = rsqrtf((float)id);
    } else if (idx < npad) {
        g_nsrc[idx] = 0.0f;   // pad rows produce clean zeros
    }
}

// phase 2+3 fused: each block recomputes the tiny 64-entry block-offset scan
__global__ void scan3_kernel(int n, int E, int nb) {
    __shared__ int sb[NBLK_MAX];
    __shared__ int sboff[NBLK_MAX];
    int t = threadIdx.x;
    if (t < NBLK_MAX) sb[t] = (t < nb) ? g_bsum[t] : 0;
    __syncthreads();
    if (t < NBLK_MAX) {
        int s = 0;
        for (int i = 0; i < t; i++) s += sb[i];
        sboff[t] = s;
    }
    __syncthreads();
    int idx = blockIdx.x * blockDim.x + t;
    if (idx < n) {
        int val = g_rowptr[idx] + sboff[idx >> 10];
        g_rowptr[idx] = val;
        g_cursor[idx] = val;
    }
    if (idx == 0) g_rowptr[n] = E;
}

__global__ void fill_kernel(const int* __restrict__ src,
                            const int* __restrict__ dst, int E) {
    int e = blockIdx.x * blockDim.x + threadIdx.x;
    if (e < E) {
        int p = atomicAdd(&g_cursor[dst[e]], 1);
        g_esrc[p] = src[e];
    }
}

// W (3 layers fp32 [k][n]) -> bf16 same layout
__global__ void convw_kernel(const float* __restrict__ Ws) {
    int i = blockIdx.x * blockDim.x + threadIdx.x;
    if (i < 3 * TILE_ELEMS / 2) {
        float2 v = ((const float2*)Ws)[i];
        ((uint32_t*)g_Wb)[i] = bf16x2(v.x, v.y);
    }
}

// attr fp32 -> bf16 (pad rows zeroed); one warp per row
__global__ void copy_attr_kernel(const float* __restrict__ attr, int n, int npad) {
    int node = (blockIdx.x * blockDim.x + threadIdx.x) >> 5;
    int lane = threadIdx.x & 31;
    if (node >= npad) return;
    float4 v = make_float4(0.f, 0.f, 0.f, 0.f);
    if (node < n) v = ((const float4*)(attr + (size_t)node * HID))[lane];
    ((uint2*)(g_hB + (size_t)node * HID))[lane] =
        make_uint2(bf16x2(v.x, v.y), bf16x2(v.z, v.w));
}

__global__ void mask_kernel(const int* __restrict__ mask_nodes,
                            const float* __restrict__ token, int nmask) {
    int w = (blockIdx.x * blockDim.x + threadIdx.x) >> 5;
    int lane = threadIdx.x & 31;
    if (w >= nmask) return;
    int node = mask_nodes[w];
    float4 v = ((const float4*)token)[lane];
    ((uint2*)(g_hB + (size_t)node * HID))[lane] =
        make_uint2(bf16x2(v.x, v.y), bf16x2(v.z, v.w));
}

// ---------------- bf16 HMMA GEMM: hs[tile] = (h_tile @ W) * nsrc ----------------
// 256 threads = 8 warps; warp w -> rows 16w..16w+15 x 128 cols.
__global__ __launch_bounds__(256) void gemm_mma_kernel(const __nv_bfloat16* __restrict__ Wb) {
    extern __shared__ __nv_bfloat16 sm[];
    __nv_bfloat16* sA = sm;                 // 128 x ASTRIDE
    __nv_bfloat16* sB = sm + 128 * ASTRIDE;
    int tid = threadIdx.x, lane = tid & 31, wid = tid >> 5;

    // load tiles: each thread owns one half-row = 64 bf16 = 128 B = 8 uint4 per buffer
    {
        int row = tid >> 1, half = tid & 1;
        const uint4* ga = (const uint4*)(g_hB + (size_t)blockIdx.x * 128 * HID
                                         + row * HID + half * 64);
        const uint4* gb = (const uint4*)(Wb + row * HID + half * 64);
        uint4* pa = (uint4*)(sA + row * ASTRIDE + half * 64);
        uint4* pb = (uint4*)(sB + row * ASTRIDE + half * 64);
        #pragma unroll
        for (int i = 0; i < 8; i++) { pa[i] = ga[i]; pb[i] = gb[i]; }
    }
    __syncthreads();

    uint32_t aaddr = smem_u32(sA)
        + (uint32_t)(((wid * 16) + ((lane >> 3) & 1) * 8 + (lane & 7)) * ASTRIDE
                     + ((lane >> 4) * 8)) * 2;
    uint32_t baddr = smem_u32(sB) + (uint32_t)((lane & 15) * ASTRIDE) * 2;

    float acc[16][4];
    #pragma unroll
    for (int j = 0; j < 16; j++)
        #pragma unroll
        for (int q = 0; q < 4; q++) acc[j][q] = 0.f;

    #pragma unroll
    for (int ks = 0; ks < 8; ks++) {
        uint32_t a0, a1, a2, a3;
        asm volatile("ldmatrix.sync.aligned.m8n8.x4.shared.b16 {%0,%1,%2,%3}, [%4];"
            : "=r"(a0), "=r"(a1), "=r"(a2), "=r"(a3) : "r"(aaddr + ks * 32));
        #pragma unroll
        for (int j = 0; j < 16; j++) {
            uint32_t b0, b1;
            asm volatile("ldmatrix.sync.aligned.m8n8.x2.trans.shared.b16 {%0,%1}, [%2];"
                : "=r"(b0), "=r"(b1)
                : "r"(baddr + (uint32_t)(ks * 16 * ASTRIDE + j * 8) * 2));
            asm volatile(
                "mma.sync.aligned.m16n8k16.row.col.f32.bf16.bf16.f32 "
                "{%0,%1,%2,%3}, {%4,%5,%6,%7}, {%8,%9}, {%0,%1,%2,%3};"
                : "+f"(acc[j][0]), "+f"(acc[j][1]), "+f"(acc[j][2]), "+f"(acc[j][3])
                : "r"(a0), "r"(a1), "r"(a2), "r"(a3), "r"(b0), "r"(b1));
        }
    }

    // epilogue: scale by nsrc, store bf16 row-major
    int r0 = blockIdx.x * 128 + wid * 16 + (lane >> 2);
    int r1 = r0 + 8;
    float s0 = g_nsrc[r0], s1 = g_nsrc[r1];
    uint32_t* o0 = (uint32_t*)(g_hs + (size_t)r0 * HID) + (lane & 3);
    uint32_t* o1 = (uint32_t*)(g_hs + (size_t)r1 * HID) + (lane & 3);
    #pragma unroll
    for (int j = 0; j < 16; j++) {
        o0[j * 4] = bf16x2(acc[j][0] * s0, acc[j][1] * s0);
        o1[j * 4] = bf16x2(acc[j][2] * s1, acc[j][3] * s1);
    }
}

// ---------------- CSR aggregation (bf16 in, fp32 accum) + norm_dst + bias + relu ----
// mode 0: write bf16 to g_hB (next layer GEMM A); mode 1: write fp32 to g_bufA
__global__ void aggregate_kernel(const float* __restrict__ bias, int n, int mode) {
    int w = (blockIdx.x * blockDim.x + threadIdx.x) >> 5;
    int lane = threadIdx.x & 31;
    if (w >= n) return;
    int beg = g_rowptr[w], end = g_rowptr[w + 1];
    float ax = 0.f, ay = 0.f, az = 0.f, aw = 0.f;
    const char* hs = (const char*)g_hs;
    int loff = lane << 3;
    int i = beg;
    for (; i + 2 <= end; i += 2) {
        int s0 = g_esrc[i], s1 = g_esrc[i + 1];
        uint2 v0 = *(const uint2*)(hs + ((size_t)s0 << 8) + loff);
        uint2 v1 = *(const uint2*)(hs + ((size_t)s1 << 8) + loff);
        ax += __uint_as_float(v0.x << 16) + __uint_as_float(v1.x << 16);
        ay += __uint_as_float(v0.x & 0xFFFF0000u) + __uint_as_float(v1.x & 0xFFFF0000u);
        az += __uint_as_float(v0.y << 16) + __uint_as_float(v1.y << 16);
        aw += __uint_as_float(v0.y & 0xFFFF0000u) + __uint_as_float(v1.y & 0xFFFF0000u);
    }
    if (i < end) {
        int s0 = g_esrc[i];
        uint2 v0 = *(const uint2*)(hs + ((size_t)s0 << 8) + loff);
        ax += __uint_as_float(v0.x << 16);
        ay += __uint_as_float(v0.x & 0xFFFF0000u);
        az += __uint_as_float(v0.y << 16);
        aw += __uint_as_float(v0.y & 0xFFFF0000u);
    }
    float nd = g_ndst[w];
    float4 b = __ldg((const float4*)bias + lane);
    float4 o;
    o.x = fmaxf(ax * nd + b.x, 0.f);
    o.y = fmaxf(ay * nd + b.y, 0.f);
    o.z = fmaxf(az * nd + b.z, 0.f);
    o.w = fmaxf(aw * nd + b.w, 0.f);
    if (mode == 0) {
        ((uint2*)(g_hB + (size_t)w * HID))[lane] =
            make_uint2(bf16x2(o.x, o.y), bf16x2(o.z, o.w));
    } else {
        ((float4*)(g_bufA + (size_t)w * HID))[lane] = o;
    }
}

// ---------------- fused decoder GEMM (masked rows only) + MSE ----------------
__global__ __launch_bounds__(256) void decode_loss_kernel(
    const float* __restrict__ h, const float* __restrict__ dW,
    const float* __restrict__ db, const float* __restrict__ attr,
    const int* __restrict__ mask_nodes, int nmask) {
    extern __shared__ float sh[];
    float* Wsh = sh;
    float* hsh = sh + HID * HID;
    __shared__ int rows[64];
    __shared__ float wpart[8];
    int tid = threadIdx.x;

    for (int i = tid; i < HID * HID / 4; i += 256)
        ((float4*)Wsh)[i] = ((const float4*)dW)[i];

    int m0 = blockIdx.x * 64;
    if (tid < 64) {
        int mi = m0 + tid;
        rows[tid] = (mi < nmask) ? mask_nodes[mi] : -1;
    }
    __syncthreads();

    for (int i = tid; i < 64 * 32; i += 256) {
        int r = i >> 5, c = i & 31;
        int node = rows[r];
        float4 v = make_float4(0.f, 0.f, 0.f, 0.f);
        if (node >= 0) v = ((const float4*)(h + (size_t)node * HID))[c];
        ((float4*)(hsh + r * HID))[c] = v;
    }
    __syncthreads();

    int trow = tid >> 5, tcol = tid & 31;
    unsigned long long acc01[8], acc23[8];
    #pragma unroll
    for (int i = 0; i < 8; i++) { acc01[i] = 0ull; acc23[i] = 0ull; }

    #pragma unroll 2
    for (int k4 = 0; k4 < HID / 4; k4++) {
        float4 a4[8];
        #pragma unroll
        for (int i = 0; i < 8; i++)
            a4[i] = ((const float4*)(hsh + (trow * 8 + i) * HID))[k4];
        #pragma unroll
        for (int kk = 0; kk < 4; kk++) {
            float4 b = ((const float4*)(Wsh + (k4 * 4 + kk) * HID))[tcol];
            unsigned long long b01 = pack2(b.x, b.y);
            unsigned long long b23 = pack2(b.z, b.w);
            #pragma unroll
            for (int i = 0; i < 8; i++) {
                float av = (kk == 0) ? a4[i].x : (kk == 1) ? a4[i].y
                         : (kk == 2) ? a4[i].z : a4[i].w;
                unsigned long long a2 = pack2(av, av);
                fma2(acc01[i], a2, b01);
                fma2(acc23[i], a2, b23);
            }
        }
    }

    float4 b4 = __ldg((const float4*)db + tcol);
    float sse = 0.f;
    #pragma unroll
    for (int i = 0; i < 8; i++) {
        int node = rows[trow * 8 + i];
        if (node >= 0) {
            float4 a = __ldg((const float4*)(attr + (size_t)node * HID) + tcol);
            float2 p01 = unpack2(acc01[i]);
            float2 p23 = unpack2(acc23[i]);
            float d0 = p01.x + b4.x - a.x;
            float d1 = p01.y + b4.y - a.y;
            float d2 = p23.x + b4.z - a.z;
            float d3 = p23.y + b4.w - a.w;
            sse += d0 * d0 + d1 * d1 + d2 * d2 + d3 * d3;
        }
    }
    #pragma unroll
    for (int o = 16; o > 0; o >>= 1)
        sse += __shfl_down_sync(0xffffffffu, sse, o);
    if ((tid & 31) == 0) wpart[tid >> 5] = sse;
    __syncthreads();
    if (tid == 0) {
        float t = 0.f;
        #pragma unroll
        for (int i = 0; i < 8; i++) t += wpart[i];
        atomicAdd(&g_loss, t);
    }
}

__global__ void finalize_kernel(float* __restrict__ out, int nmask) {
    out[0] = g_loss / (float)((size_t)nmask * HID);
}

// ---------------- host launcher ----------------
extern "C" void kernel_launch(void* const* d_in, const int* in_sizes, int n_in,
                              void* d_out, int out_size) {
    const float* attr       = (const float*)d_in[0];
    const int*   src        = (const int*)d_in[1];
    const int*   dst        = (const int*)d_in[2];
    const float* Ws         = (const float*)d_in[3];
    const float* bs         = (const float*)d_in[4];
    const float* dec_W      = (const float*)d_in[5];
    const float* dec_b      = (const float*)d_in[6];
    const float* mask_token = (const float*)d_in[7];
    const int*   mask_nodes = (const int*)d_in[8];

    int N      = in_sizes[0] / HID;
    int E      = in_sizes[1];
    int nmask  = in_sizes[8];
    int npad   = (N + 127) & ~127;
    int ntiles = npad / 128;
    int nb     = (N + SCAN_BLK - 1) / SCAN_BLK;

    float* bufA = nullptr;
    __nv_bfloat16* Wb = nullptr;
    cudaGetSymbolAddress((void**)&bufA, g_bufA);
    cudaGetSymbolAddress((void**)&Wb, g_Wb);

    const int smem_gemm = 2 * 128 * ASTRIDE * 2;                        // 69632 B
    const int smem_dec  = (HID * HID + 64 * HID) * (int)sizeof(float);  // 96 KB
    cudaFuncSetAttribute(gemm_mma_kernel,
                         cudaFuncAttributeMaxDynamicSharedMemorySize, smem_gemm);
    cudaFuncSetAttribute(decode_loss_kernel,
                         cudaFuncAttributeMaxDynamicSharedMemorySize, smem_dec);

    zero_kernel<<<(N + 255) / 256, 256>>>(N);
    count_deg_kernel<<<(E + 255) / 256, 256>>>(src, dst, E);
    scan1_kernel<<<nb, SCAN_BLK>>>(N, npad);
    scan3_kernel<<<(N + 255) / 256, 256>>>(N, E, nb);
    fill_kernel<<<(E + 255) / 256, 256>>>(src, dst, E);
    convw_kernel<<<(3 * TILE_ELEMS / 2 + 255) / 256, 256>>>(Ws);
    copy_attr_kernel<<<(npad * 32 + 255) / 256, 256>>>(attr, N, npad);
    mask_kernel<<<(nmask * 32 + 255) / 256, 256>>>(mask_nodes, mask_token, nmask);

    for (int l = 0; l < 3; l++) {
        gemm_mma_kernel<<<ntiles, 256, smem_gemm>>>(Wb + (size_t)l * TILE_ELEMS);
        aggregate_kernel<<<(N * 32 + 255) / 256, 256>>>(
            bs + (size_t)l * HID, N, (l == 2) ? 1 : 0);
    }

    decode_loss_kernel<<<(nmask + 63) / 64, 256, smem_dec>>>(
        bufA, dec_W, dec_b, attr, mask_nodes, nmask);
    finalize_kernel<<<1, 1>>>((float*)d_out, nmask);
}

// round 8
// speedup vs baseline: 1.8340x; 1.0932x over previous
#include <cuda_runtime.h>
#include <cuda_bf16.h>
#include <cstdint>

#define HID 128
#define NMAX 50000
#define NPADMAX 50048           // ceil(50000/128)*128
#define EMAX 800000
#define SCAN_BLK 1024
#define NBLK_MAX 64
#define TILE_ELEMS 16384        // 128x128
#define ASTRIDE 136             // smem row stride in bf16 elems (272B: conflict-free ldmatrix)

// ---------------- scratch (static device globals; no allocation) ----------------
__device__ __nv_bfloat16 g_hB[(size_t)NPADMAX * HID];       // h (bf16 row-major, GEMM A)
__device__ __nv_bfloat16 g_hs[(size_t)NPADMAX * HID];       // GEMM output (bf16 row-major)
__device__ __nv_bfloat16 g_Wb[4 * TILE_ELEMS];              // W bf16 [l][k][n]; slot 3 = dec_W
__device__ float g_nsrc[NPADMAX];
__device__ float g_ndst[NMAX];
__device__ int   g_degout[NMAX];
__device__ int   g_degin[NMAX];
__device__ int   g_rowptr[NMAX + 1];
__device__ int   g_cursor[NMAX];
__device__ int   g_esrc[EMAX];
__device__ int   g_bsum[NBLK_MAX];
__device__ float g_loss;
__device__ unsigned int g_done;

// ---------------- helpers ----------------
__device__ __forceinline__ uint32_t smem_u32(const void* p) {
    uint32_t a;
    asm("{ .reg .u64 t; cvta.to.shared.u64 t, %1; cvt.u32.u64 %0, t; }" : "=r"(a) : "l"(p));
    return a;
}
// bf16x2 pack: first arg -> low half
__device__ __forceinline__ uint32_t bf16x2(float lo, float hi) {
    uint32_t r;
    asm("cvt.rn.bf16x2.f32 %0, %1, %2;" : "=r"(r) : "f"(hi), "f"(lo));
    return r;
}

// ---------------- prep kernels ----------------
__global__ void zero_kernel(int n) {
    int i = blockIdx.x * blockDim.x + threadIdx.x;
    if (i < n) { g_degout[i] = 0; g_degin[i] = 0; }
    if (i == 0) { g_loss = 0.0f; g_done = 0u; }
}

__global__ void count_deg_kernel(const int* __restrict__ src,
                                 const int* __restrict__ dst, int E) {
    int e = blockIdx.x * blockDim.x + threadIdx.x;
    if (e < E) {
        atomicAdd(&g_degout[src[e]], 1);
        atomicAdd(&g_degin[dst[e]], 1);
    }
}

// phase 1: per-block exclusive scan of degin (local), block totals, fused norms
__global__ void scan1_kernel(int n, int npad) {
    __shared__ int wsum[32];
    int t = threadIdx.x, lane = t & 31, w = t >> 5;
    int idx = blockIdx.x * SCAN_BLK + t;
    int v = (idx < n) ? g_degin[idx] : 0;
    int x = v;
    #pragma unroll
    for (int o = 1; o < 32; o <<= 1) {
        int y = __shfl_up_sync(0xffffffffu, x, o);
        if (lane >= o) x += y;
    }
    if (lane == 31) wsum[w] = x;
    __syncthreads();
    if (w == 0) {
        int s = wsum[lane];
        #pragma unroll
        for (int o = 1; o < 32; o <<= 1) {
            int y = __shfl_up_sync(0xffffffffu, s, o);
            if (lane >= o) s += y;
        }
        wsum[lane] = s;
    }
    __syncthreads();
    int woff = (w > 0) ? wsum[w - 1] : 0;
    if (idx < n) g_rowptr[idx] = woff + x - v;
    if (t == 0) g_bsum[blockIdx.x] = wsum[31];
    if (idx < n) {
        int od = g_degout[idx]; if (od < 1) od = 1;
        int id = v;             if (id < 1) id = 1;
        g_nsrc[idx] = rsqrtf((float)od);
        g_ndst[idx] = rsqrtf((float)id);
    } else if (idx < npad) {
        g_nsrc[idx] = 0.0f;   // pad rows produce clean zeros
    }
}

// phase 2+3 fused: each block recomputes the tiny 64-entry block-offset scan
__global__ void scan3_kernel(int n, int E, int nb) {
    __shared__ int sb[NBLK_MAX];
    __shared__ int sboff[NBLK_MAX];
    int t = threadIdx.x;
    if (t < NBLK_MAX) sb[t] = (t < nb) ? g_bsum[t] : 0;
    __syncthreads();
    if (t < NBLK_MAX) {
        int s = 0;
        for (int i = 0; i < t; i++) s += sb[i];
        sboff[t] = s;
    }
    __syncthreads();
    int idx = blockIdx.x * blockDim.x + t;
    if (idx < n) {
        int val = g_rowptr[idx] + sboff[idx >> 10];
        g_rowptr[idx] = val;
        g_cursor[idx] = val;
    }
    if (idx == 0) g_rowptr[n] = E;
}

__global__ void fill_kernel(const int* __restrict__ src,
                            const int* __restrict__ dst, int E) {
    int e = blockIdx.x * blockDim.x + threadIdx.x;
    if (e < E) {
        int p = atomicAdd(&g_cursor[dst[e]], 1);
        g_esrc[p] = src[e];
    }
}

// fp32 [rows][128] -> bf16 same layout (generic, used for Ws and dec_W)
__global__ void convw_kernel(const float* __restrict__ W, __nv_bfloat16* __restrict__ out,
                             int n2) {
    int i = blockIdx.x * blockDim.x + threadIdx.x;
    if (i < n2) {
        float2 v = ((const float2*)W)[i];
        ((uint32_t*)out)[i] = bf16x2(v.x, v.y);
    }
}

// attr fp32 -> bf16 (pad rows zeroed); one warp per row
__global__ void copy_attr_kernel(const float* __restrict__ attr, int n, int npad) {
    int node = (blockIdx.x * blockDim.x + threadIdx.x) >> 5;
    int lane = threadIdx.x & 31;
    if (node >= npad) return;
    float4 v = make_float4(0.f, 0.f, 0.f, 0.f);
    if (node < n) v = ((const float4*)(attr + (size_t)node * HID))[lane];
    ((uint2*)(g_hB + (size_t)node * HID))[lane] =
        make_uint2(bf16x2(v.x, v.y), bf16x2(v.z, v.w));
}

__global__ void mask_kernel(const int* __restrict__ mask_nodes,
                            const float* __restrict__ token, int nmask) {
    int w = (blockIdx.x * blockDim.x + threadIdx.x) >> 5;
    int lane = threadIdx.x & 31;
    if (w >= nmask) return;
    int node = mask_nodes[w];
    float4 v = ((const float4*)token)[lane];
    ((uint2*)(g_hB + (size_t)node * HID))[lane] =
        make_uint2(bf16x2(v.x, v.y), bf16x2(v.z, v.w));
}

// ---------------- bf16 HMMA GEMM: hs[tile] = (h_tile @ W) * nsrc ----------------
// 256 threads = 8 warps; warp w -> rows 16w..16w+15 x 128 cols.
__global__ __launch_bounds__(256) void gemm_mma_kernel(const __nv_bfloat16* __restrict__ Wb) {
    extern __shared__ __nv_bfloat16 sm[];
    __nv_bfloat16* sA = sm;                 // 128 x ASTRIDE
    __nv_bfloat16* sB = sm + 128 * ASTRIDE;
    int tid = threadIdx.x, lane = tid & 31, wid = tid >> 5;

    // load tiles: each thread owns one half-row = 64 bf16 = 128 B = 8 uint4 per buffer
    {
        int row = tid >> 1, half = tid & 1;
        const uint4* ga = (const uint4*)(g_hB + (size_t)blockIdx.x * 128 * HID
                                         + row * HID + half * 64);
        const uint4* gb = (const uint4*)(Wb + row * HID + half * 64);
        uint4* pa = (uint4*)(sA + row * ASTRIDE + half * 64);
        uint4* pb = (uint4*)(sB + row * ASTRIDE + half * 64);
        #pragma unroll
        for (int i = 0; i < 8; i++) { pa[i] = ga[i]; pb[i] = gb[i]; }
    }
    __syncthreads();

    uint32_t aaddr = smem_u32(sA)
        + (uint32_t)(((wid * 16) + ((lane >> 3) & 1) * 8 + (lane & 7)) * ASTRIDE
                     + ((lane >> 4) * 8)) * 2;
    uint32_t baddr = smem_u32(sB) + (uint32_t)((lane & 15) * ASTRIDE) * 2;

    float acc[16][4];
    #pragma unroll
    for (int j = 0; j < 16; j++)
        #pragma unroll
        for (int q = 0; q < 4; q++) acc[j][q] = 0.f;

    #pragma unroll
    for (int ks = 0; ks < 8; ks++) {
        uint32_t a0, a1, a2, a3;
        asm volatile("ldmatrix.sync.aligned.m8n8.x4.shared.b16 {%0,%1,%2,%3}, [%4];"
            : "=r"(a0), "=r"(a1), "=r"(a2), "=r"(a3) : "r"(aaddr + ks * 32));
        #pragma unroll
        for (int j = 0; j < 16; j++) {
            uint32_t b0, b1;
            asm volatile("ldmatrix.sync.aligned.m8n8.x2.trans.shared.b16 {%0,%1}, [%2];"
                : "=r"(b0), "=r"(b1)
                : "r"(baddr + (uint32_t)(ks * 16 * ASTRIDE + j * 8) * 2));
            asm volatile(
                "mma.sync.aligned.m16n8k16.row.col.f32.bf16.bf16.f32 "
                "{%0,%1,%2,%3}, {%4,%5,%6,%7}, {%8,%9}, {%0,%1,%2,%3};"
                : "+f"(acc[j][0]), "+f"(acc[j][1]), "+f"(acc[j][2]), "+f"(acc[j][3])
                : "r"(a0), "r"(a1), "r"(a2), "r"(a3), "r"(b0), "r"(b1));
        }
    }

    // epilogue: scale by nsrc, store bf16 row-major
    int r0 = blockIdx.x * 128 + wid * 16 + (lane >> 2);
    int r1 = r0 + 8;
    float s0 = g_nsrc[r0], s1 = g_nsrc[r1];
    uint32_t* o0 = (uint32_t*)(g_hs + (size_t)r0 * HID) + (lane & 3);
    uint32_t* o1 = (uint32_t*)(g_hs + (size_t)r1 * HID) + (lane & 3);
    #pragma unroll
    for (int j = 0; j < 16; j++) {
        o0[j * 4] = bf16x2(acc[j][0] * s0, acc[j][1] * s0);
        o1[j * 4] = bf16x2(acc[j][2] * s1, acc[j][3] * s1);
    }
}

// ---------------- CSR aggregation (bf16 in, fp32 accum) + norm_dst + bias + relu ----
__global__ void aggregate_kernel(const float* __restrict__ bias, int n) {
    int w = (blockIdx.x * blockDim.x + threadIdx.x) >> 5;
    int lane = threadIdx.x & 31;
    if (w >= n) return;
    int beg = g_rowptr[w], end = g_rowptr[w + 1];
    float ax = 0.f, ay = 0.f, az = 0.f, aw = 0.f;
    const char* hs = (const char*)g_hs;
    int loff = lane << 3;
    int i = beg;
    for (; i + 2 <= end; i += 2) {
        int s0 = g_esrc[i], s1 = g_esrc[i + 1];
        uint2 v0 = *(const uint2*)(hs + ((size_t)s0 << 8) + loff);
        uint2 v1 = *(const uint2*)(hs + ((size_t)s1 << 8) + loff);
        ax += __uint_as_float(v0.x << 16) + __uint_as_float(v1.x << 16);
        ay += __uint_as_float(v0.x & 0xFFFF0000u) + __uint_as_float(v1.x & 0xFFFF0000u);
        az += __uint_as_float(v0.y << 16) + __uint_as_float(v1.y << 16);
        aw += __uint_as_float(v0.y & 0xFFFF0000u) + __uint_as_float(v1.y & 0xFFFF0000u);
    }
    if (i < end) {
        int s0 = g_esrc[i];
        uint2 v0 = *(const uint2*)(hs + ((size_t)s0 << 8) + loff);
        ax += __uint_as_float(v0.x << 16);
        ay += __uint_as_float(v0.x & 0xFFFF0000u);
        az += __uint_as_float(v0.y << 16);
        aw += __uint_as_float(v0.y & 0xFFFF0000u);
    }
    float nd = g_ndst[w];
    float4 b = __ldg((const float4*)bias + lane);
    float4 o;
    o.x = fmaxf(ax * nd + b.x, 0.f);
    o.y = fmaxf(ay * nd + b.y, 0.f);
    o.z = fmaxf(az * nd + b.z, 0.f);
    o.w = fmaxf(aw * nd + b.w, 0.f);
    ((uint2*)(g_hB + (size_t)w * HID))[lane] =
        make_uint2(bf16x2(o.x, o.y), bf16x2(o.z, o.w));
}

// ---------------- HMMA decoder (128 masked rows/block) + fused MSE + finalize ------
__global__ __launch_bounds__(256) void decode_mma_kernel(
    const __nv_bfloat16* __restrict__ WdB, const float* __restrict__ db,
    const float* __restrict__ attr, const int* __restrict__ mask_nodes,
    int nmask, float* __restrict__ out, int nblocks) {
    extern __shared__ __nv_bfloat16 sm[];
    __nv_bfloat16* sA = sm;                 // 128 x ASTRIDE (gathered h rows)
    __nv_bfloat16* sB = sm + 128 * ASTRIDE; // dec_W
    __shared__ int rows[128];
    __shared__ float wpart[8];
    int tid = threadIdx.x, lane = tid & 31, wid = tid >> 5;

    int m0 = blockIdx.x * 128;
    if (tid < 128) {
        int mi = m0 + tid;
        rows[tid] = (mi < nmask) ? mask_nodes[mi] : -1;
    }
    __syncthreads();

    // gather A rows (bf16) + load dec_W
    {
        int row = tid >> 1, half = tid & 1;
        int node = rows[row];
        uint4* pa = (uint4*)(sA + row * ASTRIDE + half * 64);
        const uint4* gb = (const uint4*)(WdB + row * HID + half * 64);
        uint4* pb = (uint4*)(sB + row * ASTRIDE + half * 64);
        if (node >= 0) {
            const uint4* ga = (const uint4*)(g_hB + (size_t)node * HID + half * 64);
            #pragma unroll
            for (int i = 0; i < 8; i++) { pa[i] = ga[i]; pb[i] = gb[i]; }
        } else {
            uint4 z = make_uint4(0, 0, 0, 0);
            #pragma unroll
            for (int i = 0; i < 8; i++) { pa[i] = z; pb[i] = gb[i]; }
        }
    }
    __syncthreads();

    uint32_t aaddr = smem_u32(sA)
        + (uint32_t)(((wid * 16) + ((lane >> 3) & 1) * 8 + (lane & 7)) * ASTRIDE
                     + ((lane >> 4) * 8)) * 2;
    uint32_t baddr = smem_u32(sB) + (uint32_t)((lane & 15) * ASTRIDE) * 2;

    float acc[16][4];
    #pragma unroll
    for (int j = 0; j < 16; j++)
        #pragma unroll
        for (int q = 0; q < 4; q++) acc[j][q] = 0.f;

    #pragma unroll
    for (int ks = 0; ks < 8; ks++) {
        uint32_t a0, a1, a2, a3;
        asm volatile("ldmatrix.sync.aligned.m8n8.x4.shared.b16 {%0,%1,%2,%3}, [%4];"
            : "=r"(a0), "=r"(a1), "=r"(a2), "=r"(a3) : "r"(aaddr + ks * 32));
        #pragma unroll
        for (int j = 0; j < 16; j++) {
            uint32_t b0, b1;
            asm volatile("ldmatrix.sync.aligned.m8n8.x2.trans.shared.b16 {%0,%1}, [%2];"
                : "=r"(b0), "=r"(b1)
                : "r"(baddr + (uint32_t)(ks * 16 * ASTRIDE + j * 8) * 2));
            asm volatile(
                "mma.sync.aligned.m16n8k16.row.col.f32.bf16.bf16.f32 "
                "{%0,%1,%2,%3}, {%4,%5,%6,%7}, {%8,%9}, {%0,%1,%2,%3};"
                : "+f"(acc[j][0]), "+f"(acc[j][1]), "+f"(acc[j][2]), "+f"(acc[j][3])
                : "r"(a0), "r"(a1), "r"(a2), "r"(a3), "r"(b0), "r"(b1));
        }
    }

    // fused bias + MSE against fp32 attr
    int rl0 = wid * 16 + (lane >> 2);
    int rl1 = rl0 + 8;
    int node0 = rows[rl0], node1 = rows[rl1];
    float sse = 0.f;
    #pragma unroll
    for (int j = 0; j < 16; j++) {
        int c = j * 8 + (lane & 3) * 2;
        float2 dbv = __ldg((const float2*)(db + c));
        if (node0 >= 0) {
            float2 a = __ldg((const float2*)(attr + (size_t)node0 * HID + c));
            float d0 = acc[j][0] + dbv.x - a.x;
            float d1 = acc[j][1] + dbv.y - a.y;
            sse += d0 * d0 + d1 * d1;
        }
        if (node1 >= 0) {
            float2 a = __ldg((const float2*)(attr + (size_t)node1 * HID + c));
            float d2 = acc[j][2] + dbv.x - a.x;
            float d3 = acc[j][3] + dbv.y - a.y;
            sse += d2 * d2 + d3 * d3;
        }
    }
    #pragma unroll
    for (int o = 16; o > 0; o >>= 1)
        sse += __shfl_down_sync(0xffffffffu, sse, o);
    if (lane == 0) wpart[wid] = sse;
    __syncthreads();
    if (tid == 0) {
        float t = 0.f;
        #pragma unroll
        for (int i = 0; i < 8; i++) t += wpart[i];
        atomicAdd(&g_loss, t);
        __threadfence();
        unsigned int done = atomicAdd(&g_done, 1u);
        if (done == (unsigned int)(nblocks - 1)) {
            out[0] = g_loss / (float)((size_t)nmask * HID);
        }
    }
}

// ---------------- host launcher ----------------
extern "C" void kernel_launch(void* const* d_in, const int* in_sizes, int n_in,
                              void* d_out, int out_size) {
    const float* attr       = (const float*)d_in[0];
    const int*   src        = (const int*)d_in[1];
    const int*   dst        = (const int*)d_in[2];
    const float* Ws         = (const float*)d_in[3];
    const float* bs         = (const float*)d_in[4];
    const float* dec_W      = (const float*)d_in[5];
    const float* dec_b      = (const float*)d_in[6];
    const float* mask_token = (const float*)d_in[7];
    const int*   mask_nodes = (const int*)d_in[8];

    int N      = in_sizes[0] / HID;
    int E      = in_sizes[1];
    int nmask  = in_sizes[8];
    int npad   = (N + 127) & ~127;
    int ntiles = npad / 128;
    int nb     = (N + SCAN_BLK - 1) / SCAN_BLK;
    int ndec   = (nmask + 127) / 128;

    __nv_bfloat16* Wb = nullptr;
    cudaGetSymbolAddress((void**)&Wb, g_Wb);

    const int smem_gemm = 2 * 128 * ASTRIDE * 2;   // 69632 B
    cudaFuncSetAttribute(gemm_mma_kernel,
                         cudaFuncAttributeMaxDynamicSharedMemorySize, smem_gemm);
    cudaFuncSetAttribute(decode_mma_kernel,
                         cudaFuncAttributeMaxDynamicSharedMemorySize, smem_gemm);

    zero_kernel<<<(N + 255) / 256, 256>>>(N);
    count_deg_kernel<<<(E + 255) / 256, 256>>>(src, dst, E);
    scan1_kernel<<<nb, SCAN_BLK>>>(N, npad);
    scan3_kernel<<<(N + 255) / 256, 256>>>(N, E, nb);
    fill_kernel<<<(E + 255) / 256, 256>>>(src, dst, E);
    convw_kernel<<<(3 * TILE_ELEMS / 2 + 255) / 256, 256>>>(Ws, Wb, 3 * TILE_ELEMS / 2);
    convw_kernel<<<(TILE_ELEMS / 2 + 255) / 256, 256>>>(
        dec_W, Wb + 3 * (size_t)TILE_ELEMS, TILE_ELEMS / 2);
    copy_attr_kernel<<<(npad * 32 + 255) / 256, 256>>>(attr, N, npad);
    mask_kernel<<<(nmask * 32 + 255) / 256, 256>>>(mask_nodes, mask_token, nmask);

    for (int l = 0; l < 3; l++) {
        gemm_mma_kernel<<<ntiles, 256, smem_gemm>>>(Wb + (size_t)l * TILE_ELEMS);
        aggregate_kernel<<<(N * 32 + 255) / 256, 256>>>(bs + (size_t)l * HID, N);
    }

    decode_mma_kernel<<<ndec, 256, smem_gemm>>>(
        Wb + 3 * (size_t)TILE_ELEMS, dec_b, attr, mask_nodes, nmask,
        (float*)d_out, ndec);
}

// round 9
// speedup vs baseline: 1.8645x; 1.0166x over previous
#include <cuda_runtime.h>
#include <cuda_bf16.h>
#include <cuda_fp16.h>
#include <cstdint>

#define HID 128
#define NMAX 50000
#define NPADMAX 50048           // ceil(50000/128)*128
#define EMAX 800000
#define SCAN_BLK 1024
#define NBLK_MAX 64
#define TILE_ELEMS 16384        // 128x128
#define ASTRIDE 136             // smem row stride in bf16 elems (272B: conflict-free ldmatrix)

// ---------------- scratch (static device globals; no allocation) ----------------
__device__ __nv_bfloat16 g_hB[(size_t)NPADMAX * HID];       // h (bf16 row-major, GEMM A)
__device__ uint8_t       g_hs8[(size_t)NPADMAX * HID];      // GEMM output (e4m3 row-major)
__device__ __nv_bfloat16 g_Wb[4 * TILE_ELEMS];              // W bf16 [l][k][n]; slot 3 = dec_W
__device__ float g_nsrc[NPADMAX];
__device__ float g_ndst[NMAX];
__device__ int   g_degout[NMAX];
__device__ int   g_degin[NMAX];
__device__ int   g_rowptr[NMAX];                            // block-LOCAL exclusive prefix
__device__ int   g_cursor[NMAX];                            // block-LOCAL fill cursor
__device__ int   g_esrc[EMAX];
__device__ int   g_bsum[NBLK_MAX];
__device__ int   g_boff[NBLK_MAX];                          // global offset per 1024-node block
__device__ float g_loss;
__device__ unsigned int g_done;

// ---------------- helpers ----------------
__device__ __forceinline__ uint32_t smem_u32(const void* p) {
    uint32_t a;
    asm("{ .reg .u64 t; cvta.to.shared.u64 t, %1; cvt.u32.u64 %0, t; }" : "=r"(a) : "l"(p));
    return a;
}
// bf16x2 pack: first arg -> low half
__device__ __forceinline__ uint32_t bf16x2(float lo, float hi) {
    uint32_t r;
    asm("cvt.rn.bf16x2.f32 %0, %1, %2;" : "=r"(r) : "f"(hi), "f"(lo));
    return r;
}
// e4m3 pair pack: lo -> low byte
__device__ __forceinline__ uint16_t e4m3x2(float lo, float hi) {
    uint16_t r;
    asm("cvt.rn.satfinite.e4m3x2.f32 %0, %1, %2;" : "=h"(r) : "f"(hi), "f"(lo));
    return r;
}
// 4 packed e4m3 -> float4 (via exact f16 intermediate)
__device__ __forceinline__ float4 fp8x4_to_float4(uint32_t u) {
    uint32_t a, b;
    asm("cvt.rn.f16x2.e4m3x2 %0, %1;" : "=r"(a) : "h"((unsigned short)(u & 0xFFFFu)));
    asm("cvt.rn.f16x2.e4m3x2 %0, %1;" : "=r"(b) : "h"((unsigned short)(u >> 16)));
    __half2 ha = *reinterpret_cast<__half2*>(&a);
    __half2 hb = *reinterpret_cast<__half2*>(&b);
    float2 fa = __half22float2(ha), fb = __half22float2(hb);
    return make_float4(fa.x, fa.y, fb.x, fb.y);
}

// ---------------- prep kernels ----------------
__global__ void zero_kernel(int n) {
    int i = blockIdx.x * blockDim.x + threadIdx.x;
    if (i < n) { g_degout[i] = 0; g_degin[i] = 0; }
    if (i == 0) { g_loss = 0.0f; g_done = 0u; }
}

__global__ void count_deg_kernel(const int* __restrict__ src,
                                 const int* __restrict__ dst, int E) {
    int e = blockIdx.x * blockDim.x + threadIdx.x;
    if (e < E) {
        atomicAdd(&g_degout[src[e]], 1);
        atomicAdd(&g_degin[dst[e]], 1);
    }
}

// phase 1: per-block LOCAL exclusive scan of degin, block totals, fused norms
__global__ void scan1_kernel(int n, int npad) {
    __shared__ int wsum[32];
    int t = threadIdx.x, lane = t & 31, w = t >> 5;
    int idx = blockIdx.x * SCAN_BLK + t;
    int v = (idx < n) ? g_degin[idx] : 0;
    int x = v;
    #pragma unroll
    for (int o = 1; o < 32; o <<= 1) {
        int y = __shfl_up_sync(0xffffffffu, x, o);
        if (lane >= o) x += y;
    }
    if (lane == 31) wsum[w] = x;
    __syncthreads();
    if (w == 0) {
        int s = wsum[lane];
        #pragma unroll
        for (int o = 1; o < 32; o <<= 1) {
            int y = __shfl_up_sync(0xffffffffu, s, o);
            if (lane >= o) s += y;
        }
        wsum[lane] = s;
    }
    __syncthreads();
    int woff = (w > 0) ? wsum[w - 1] : 0;
    if (idx < n) {
        int loc = woff + x - v;
        g_rowptr[idx] = loc;
        g_cursor[idx] = loc;
    }
    if (t == 0) g_bsum[blockIdx.x] = wsum[31];
    if (idx < n) {
        int od = g_degout[idx]; if (od < 1) od = 1;
        int id = v;             if (id < 1) id = 1;
        g_nsrc[idx] = rsqrtf((float)od);
        g_ndst[idx] = rsqrtf((float)id);
    } else if (idx < npad) {
        g_nsrc[idx] = 0.0f;   // pad rows produce clean zeros
    }
}

// phase 2: single 64-thread block -> exclusive scan of block sums
__global__ void scan2_kernel(int nb) {
    __shared__ int wtot[2];
    int t = threadIdx.x, lane = t & 31, w = t >> 5;
    int v = (t < nb) ? g_bsum[t] : 0;
    int x = v;
    #pragma unroll
    for (int o = 1; o < 32; o <<= 1) {
        int y = __shfl_up_sync(0xffffffffu, x, o);
        if (lane >= o) x += y;
    }
    if (lane == 31) wtot[w] = x;
    __syncthreads();
    int add = (w == 1) ? wtot[0] : 0;
    if (t < nb) g_boff[t] = add + x - v;
}

__global__ void fill_kernel(const int* __restrict__ src,
                            const int* __restrict__ dst, int E) {
    int e = blockIdx.x * blockDim.x + threadIdx.x;
    if (e < E) {
        int d = dst[e];
        int p = atomicAdd(&g_cursor[d], 1) + g_boff[d >> 10];
        g_esrc[p] = src[e];
    }
}

// fp32 -> bf16 weights: layers 0..2 from Ws, slot 3 from dec_W
__global__ void convw_kernel(const float* __restrict__ Ws, const float* __restrict__ dW) {
    int i = blockIdx.x * blockDim.x + threadIdx.x;
    const int n3 = 3 * TILE_ELEMS / 2;
    if (i < n3) {
        float2 v = ((const float2*)Ws)[i];
        ((uint32_t*)g_Wb)[i] = bf16x2(v.x, v.y);
    } else if (i < n3 + TILE_ELEMS / 2) {
        float2 v = ((const float2*)dW)[i - n3];
        ((uint32_t*)g_Wb)[i] = bf16x2(v.x, v.y);
    }
}

// attr fp32 -> bf16 (pad rows zeroed); one warp per row
__global__ void copy_attr_kernel(const float* __restrict__ attr, int n, int npad) {
    int node = (blockIdx.x * blockDim.x + threadIdx.x) >> 5;
    int lane = threadIdx.x & 31;
    if (node >= npad) return;
    float4 v = make_float4(0.f, 0.f, 0.f, 0.f);
    if (node < n) v = ((const float4*)(attr + (size_t)node * HID))[lane];
    ((uint2*)(g_hB + (size_t)node * HID))[lane] =
        make_uint2(bf16x2(v.x, v.y), bf16x2(v.z, v.w));
}

__global__ void mask_kernel(const int* __restrict__ mask_nodes,
                            const float* __restrict__ token, int nmask) {
    int w = (blockIdx.x * blockDim.x + threadIdx.x) >> 5;
    int lane = threadIdx.x & 31;
    if (w >= nmask) return;
    int node = mask_nodes[w];
    float4 v = ((const float4*)token)[lane];
    ((uint2*)(g_hB + (size_t)node * HID))[lane] =
        make_uint2(bf16x2(v.x, v.y), bf16x2(v.z, v.w));
}

// ---------------- bf16 HMMA GEMM: hs8[tile] = e4m3((h_tile @ W) * nsrc) -----------
// 256 threads = 8 warps; warp w -> rows 16w..16w+15 x 128 cols.
__global__ __launch_bounds__(256) void gemm_mma_kernel(const __nv_bfloat16* __restrict__ Wb) {
    extern __shared__ __nv_bfloat16 sm[];
    __nv_bfloat16* sA = sm;                 // 128 x ASTRIDE
    __nv_bfloat16* sB = sm + 128 * ASTRIDE;
    int tid = threadIdx.x, lane = tid & 31, wid = tid >> 5;

    // load tiles: each thread owns one half-row = 64 bf16 = 128 B = 8 uint4 per buffer
    {
        int row = tid >> 1, half = tid & 1;
        const uint4* ga = (const uint4*)(g_hB + (size_t)blockIdx.x * 128 * HID
                                         + row * HID + half * 64);
        const uint4* gb = (const uint4*)(Wb + row * HID + half * 64);
        uint4* pa = (uint4*)(sA + row * ASTRIDE + half * 64);
        uint4* pb = (uint4*)(sB + row * ASTRIDE + half * 64);
        #pragma unroll
        for (int i = 0; i < 8; i++) { pa[i] = ga[i]; pb[i] = gb[i]; }
    }
    __syncthreads();

    uint32_t aaddr = smem_u32(sA)
        + (uint32_t)(((wid * 16) + ((lane >> 3) & 1) * 8 + (lane & 7)) * ASTRIDE
                     + ((lane >> 4) * 8)) * 2;
    uint32_t baddr = smem_u32(sB) + (uint32_t)((lane & 15) * ASTRIDE) * 2;

    float acc[16][4];
    #pragma unroll
    for (int j = 0; j < 16; j++)
        #pragma unroll
        for (int q = 0; q < 4; q++) acc[j][q] = 0.f;

    #pragma unroll
    for (int ks = 0; ks < 8; ks++) {
        uint32_t a0, a1, a2, a3;
        asm volatile("ldmatrix.sync.aligned.m8n8.x4.shared.b16 {%0,%1,%2,%3}, [%4];"
            : "=r"(a0), "=r"(a1), "=r"(a2), "=r"(a3) : "r"(aaddr + ks * 32));
        #pragma unroll
        for (int j = 0; j < 16; j++) {
            uint32_t b0, b1;
            asm volatile("ldmatrix.sync.aligned.m8n8.x2.trans.shared.b16 {%0,%1}, [%2];"
                : "=r"(b0), "=r"(b1)
                : "r"(baddr + (uint32_t)(ks * 16 * ASTRIDE + j * 8) * 2));
            asm volatile(
                "mma.sync.aligned.m16n8k16.row.col.f32.bf16.bf16.f32 "
                "{%0,%1,%2,%3}, {%4,%5,%6,%7}, {%8,%9}, {%0,%1,%2,%3};"
                : "+f"(acc[j][0]), "+f"(acc[j][1]), "+f"(acc[j][2]), "+f"(acc[j][3])
                : "r"(a0), "r"(a1), "r"(a2), "r"(a3), "r"(b0), "r"(b1));
        }
    }

    // epilogue: scale by nsrc, store e4m3 row-major
    int r0 = blockIdx.x * 128 + wid * 16 + (lane >> 2);
    int r1 = r0 + 8;
    float s0 = g_nsrc[r0], s1 = g_nsrc[r1];
    uint8_t* o0 = g_hs8 + (size_t)r0 * HID;
    uint8_t* o1 = g_hs8 + (size_t)r1 * HID;
    int cbase = (lane & 3) * 2;
    #pragma unroll
    for (int j = 0; j < 16; j++) {
        int c = j * 8 + cbase;
        *(uint16_t*)(o0 + c) = e4m3x2(acc[j][0] * s0, acc[j][1] * s0);
        *(uint16_t*)(o1 + c) = e4m3x2(acc[j][2] * s1, acc[j][3] * s1);
    }
}

// ---------------- CSR aggregation (e4m3 in, fp32 accum) + norm_dst + bias + relu ---
__global__ void aggregate_kernel(const float* __restrict__ bias, int n, int E) {
    int w = (blockIdx.x * blockDim.x + threadIdx.x) >> 5;
    int lane = threadIdx.x & 31;
    if (w >= n) return;
    int beg = g_rowptr[w] + g_boff[w >> 10];
    int end = (w == n - 1) ? E : g_rowptr[w + 1] + g_boff[(w + 1) >> 10];
    float ax = 0.f, ay = 0.f, az = 0.f, aw = 0.f;
    int loff = lane << 2;
    int i = beg;
    for (; i + 2 <= end; i += 2) {
        int s0 = g_esrc[i], s1 = g_esrc[i + 1];
        uint32_t u0 = *(const uint32_t*)(g_hs8 + ((size_t)s0 << 7) + loff);
        uint32_t u1 = *(const uint32_t*)(g_hs8 + ((size_t)s1 << 7) + loff);
        float4 f0 = fp8x4_to_float4(u0);
        float4 f1 = fp8x4_to_float4(u1);
        ax += f0.x + f1.x; ay += f0.y + f1.y;
        az += f0.z + f1.z; aw += f0.w + f1.w;
    }
    if (i < end) {
        int s0 = g_esrc[i];
        uint32_t u0 = *(const uint32_t*)(g_hs8 + ((size_t)s0 << 7) + loff);
        float4 f0 = fp8x4_to_float4(u0);
        ax += f0.x; ay += f0.y; az += f0.z; aw += f0.w;
    }
    float nd = g_ndst[w];
    float4 b = __ldg((const float4*)bias + lane);
    float4 o;
    o.x = fmaxf(ax * nd + b.x, 0.f);
    o.y = fmaxf(ay * nd + b.y, 0.f);
    o.z = fmaxf(az * nd + b.z, 0.f);
    o.w = fmaxf(aw * nd + b.w, 0.f);
    ((uint2*)(g_hB + (size_t)w * HID))[lane] =
        make_uint2(bf16x2(o.x, o.y), bf16x2(o.z, o.w));
}

// ---------------- HMMA decoder (128 masked rows/block) + fused MSE + finalize ------
__global__ __launch_bounds__(256) void decode_mma_kernel(
    const __nv_bfloat16* __restrict__ WdB, const float* __restrict__ db,
    const float* __restrict__ attr, const int* __restrict__ mask_nodes,
    int nmask, float* __restrict__ out, int nblocks) {
    extern __shared__ __nv_bfloat16 sm[];
    __nv_bfloat16* sA = sm;                 // 128 x ASTRIDE (gathered h rows)
    __nv_bfloat16* sB = sm + 128 * ASTRIDE; // dec_W
    __shared__ int rows[128];
    __shared__ float wpart[8];
    int tid = threadIdx.x, lane = tid & 31, wid = tid >> 5;

    int m0 = blockIdx.x * 128;
    if (tid < 128) {
        int mi = m0 + tid;
        rows[tid] = (mi < nmask) ? mask_nodes[mi] : -1;
    }
    __syncthreads();

    // gather A rows (bf16) + load dec_W
    {
        int row = tid >> 1, half = tid & 1;
        int node = rows[row];
        uint4* pa = (uint4*)(sA + row * ASTRIDE + half * 64);
        const uint4* gb = (const uint4*)(WdB + row * HID + half * 64);
        uint4* pb = (uint4*)(sB + row * ASTRIDE + half * 64);
        if (node >= 0) {
            const uint4* ga = (const uint4*)(g_hB + (size_t)node * HID + half * 64);
            #pragma unroll
            for (int i = 0; i < 8; i++) { pa[i] = ga[i]; pb[i] = gb[i]; }
        } else {
            uint4 z = make_uint4(0, 0, 0, 0);
            #pragma unroll
            for (int i = 0; i < 8; i++) { pa[i] = z; pb[i] = gb[i]; }
        }
    }
    __syncthreads();

    uint32_t aaddr = smem_u32(sA)
        + (uint32_t)(((wid * 16) + ((lane >> 3) & 1) * 8 + (lane & 7)) * ASTRIDE
                     + ((lane >> 4) * 8)) * 2;
    uint32_t baddr = smem_u32(sB) + (uint32_t)((lane & 15) * ASTRIDE) * 2;

    float acc[16][4];
    #pragma unroll
    for (int j = 0; j < 16; j++)
        #pragma unroll
        for (int q = 0; q < 4; q++) acc[j][q] = 0.f;

    #pragma unroll
    for (int ks = 0; ks < 8; ks++) {
        uint32_t a0, a1, a2, a3;
        asm volatile("ldmatrix.sync.aligned.m8n8.x4.shared.b16 {%0,%1,%2,%3}, [%4];"
            : "=r"(a0), "=r"(a1), "=r"(a2), "=r"(a3) : "r"(aaddr + ks * 32));
        #pragma unroll
        for (int j = 0; j < 16; j++) {
            uint32_t b0, b1;
            asm volatile("ldmatrix.sync.aligned.m8n8.x2.trans.shared.b16 {%0,%1}, [%2];"
                : "=r"(b0), "=r"(b1)
                : "r"(baddr + (uint32_t)(ks * 16 * ASTRIDE + j * 8) * 2));
            asm volatile(
                "mma.sync.aligned.m16n8k16.row.col.f32.bf16.bf16.f32 "
                "{%0,%1,%2,%3}, {%4,%5,%6,%7}, {%8,%9}, {%0,%1,%2,%3};"
                : "+f"(acc[j][0]), "+f"(acc[j][1]), "+f"(acc[j][2]), "+f"(acc[j][3])
                : "r"(a0), "r"(a1), "r"(a2), "r"(a3), "r"(b0), "r"(b1));
        }
    }

    // fused bias + MSE against fp32 attr
    int rl0 = wid * 16 + (lane >> 2);
    int rl1 = rl0 + 8;
    int node0 = rows[rl0], node1 = rows[rl1];
    float sse = 0.f;
    #pragma unroll
    for (int j = 0; j < 16; j++) {
        int c = j * 8 + (lane & 3) * 2;
        float2 dbv = __ldg((const float2*)(db + c));
        if (node0 >= 0) {
            float2 a = __ldg((const float2*)(attr + (size_t)node0 * HID + c));
            float d0 = acc[j][0] + dbv.x - a.x;
            float d1 = acc[j][1] + dbv.y - a.y;
            sse += d0 * d0 + d1 * d1;
        }
        if (node1 >= 0) {
            float2 a = __ldg((const float2*)(attr + (size_t)node1 * HID + c));
            float d2 = acc[j][2] + dbv.x - a.x;
            float d3 = acc[j][3] + dbv.y - a.y;
            sse += d2 * d2 + d3 * d3;
        }
    }
    #pragma unroll
    for (int o = 16; o > 0; o >>= 1)
        sse += __shfl_down_sync(0xffffffffu, sse, o);
    if (lane == 0) wpart[wid] = sse;
    __syncthreads();
    if (tid == 0) {
        float t = 0.f;
        #pragma unroll
        for (int i = 0; i < 8; i++) t += wpart[i];
        atomicAdd(&g_loss, t);
        __threadfence();
        unsigned int done = atomicAdd(&g_done, 1u);
        if (done == (unsigned int)(nblocks - 1)) {
            out[0] = g_loss / (float)((size_t)nmask * HID);
        }
    }
}

// ---------------- host launcher ----------------
extern "C" void kernel_launch(void* const* d_in, const int* in_sizes, int n_in,
                              void* d_out, int out_size) {
    const float* attr       = (const float*)d_in[0];
    const int*   src        = (const int*)d_in[1];
    const int*   dst        = (const int*)d_in[2];
    const float* Ws         = (const float*)d_in[3];
    const float* bs         = (const float*)d_in[4];
    const float* dec_W      = (const float*)d_in[5];
    const float* dec_b      = (const float*)d_in[6];
    const float* mask_token = (const float*)d_in[7];
    const int*   mask_nodes = (const int*)d_in[8];

    int N      = in_sizes[0] / HID;
    int E      = in_sizes[1];
    int nmask  = in_sizes[8];
    int npad   = (N + 127) & ~127;
    int ntiles = npad / 128;
    int nb     = (N + SCAN_BLK - 1) / SCAN_BLK;
    int ndec   = (nmask + 127) / 128;

    __nv_bfloat16* Wb = nullptr;
    cudaGetSymbolAddress((void**)&Wb, g_Wb);

    const int smem_gemm = 2 * 128 * ASTRIDE * 2;   // 69632 B
    cudaFuncSetAttribute(gemm_mma_kernel,
                         cudaFuncAttributeMaxDynamicSharedMemorySize, smem_gemm);
    cudaFuncSetAttribute(decode_mma_kernel,
                         cudaFuncAttributeMaxDynamicSharedMemorySize, smem_gemm);

    zero_kernel<<<(N + 255) / 256, 256>>>(N);
    count_deg_kernel<<<(E + 255) / 256, 256>>>(src, dst, E);
    scan1_kernel<<<nb, SCAN_BLK>>>(N, npad);
    scan2_kernel<<<1, 64>>>(nb);
    fill_kernel<<<(E + 255) / 256, 256>>>(src, dst, E);
    convw_kernel<<<(4 * TILE_ELEMS / 2 + 255) / 256, 256>>>(Ws, dec_W);
    copy_attr_kernel<<<(npad * 32 + 255) / 256, 256>>>(attr, N, npad);
    mask_kernel<<<(nmask * 32 + 255) / 256, 256>>>(mask_nodes, mask_token, nmask);

    for (int l = 0; l < 3; l++) {
        gemm_mma_kernel<<<ntiles, 256, smem_gemm>>>(Wb + (size_t)l * TILE_ELEMS);
        aggregate_kernel<<<(N * 32 + 255) / 256, 256>>>(bs + (size_t)l * HID, N, E);
    }

    decode_mma_kernel<<<ndec, 256, smem_gemm>>>(
        Wb + 3 * (size_t)TILE_ELEMS, dec_b, attr, mask_nodes, nmask,
        (float*)d_out, ndec);
}

// round 10
// speedup vs baseline: 1.9356x; 1.0381x over previous
#include <cuda_runtime.h>
#include <cuda_bf16.h>
#include <cstdint>

#define HID 128
#define NMAX 50000
#define NPADMAX 50048           // ceil(50000/128)*128
#define EMAX 800000
#define SCAN_BLK 1024
#define NBLK_MAX 64
#define TILE_ELEMS 16384        // 128x128
#define ASTRIDE 136             // smem row stride in bf16 elems (272B: conflict-free ldmatrix)

// ---------------- scratch (static device globals; no allocation) ----------------
__device__ __nv_bfloat16 g_hB[(size_t)NPADMAX * HID];       // h (bf16 row-major, GEMM A)
__device__ __nv_bfloat16 g_hs[(size_t)NPADMAX * HID];       // GEMM output (bf16 row-major)
__device__ __nv_bfloat16 g_Wb[4 * TILE_ELEMS];              // W bf16 [l][k][n]; slot 3 = dec_W
__device__ float g_nsrc[NPADMAX];
__device__ float g_ndst[NMAX];
__device__ int   g_degout[NMAX];
__device__ int   g_degin[NMAX];
__device__ int   g_rowptr[NMAX];                            // block-LOCAL exclusive prefix
__device__ int   g_cursor[NMAX];                            // block-LOCAL fill cursor
__device__ int   g_esrc[EMAX];
__device__ int   g_bsum[NBLK_MAX];
__device__ float g_loss;
__device__ unsigned int g_done;

// ---------------- helpers ----------------
__device__ __forceinline__ uint32_t smem_u32(const void* p) {
    uint32_t a;
    asm("{ .reg .u64 t; cvta.to.shared.u64 t, %1; cvt.u32.u64 %0, t; }" : "=r"(a) : "l"(p));
    return a;
}
// bf16x2 pack: first arg -> low half
__device__ __forceinline__ uint32_t bf16x2(float lo, float hi) {
    uint32_t r;
    asm("cvt.rn.bf16x2.f32 %0, %1, %2;" : "=r"(r) : "f"(hi), "f"(lo));
    return r;
}
__device__ __forceinline__ uint32_t hadd2bf(uint32_t a, uint32_t b) {
    uint32_t r;
    asm("add.rn.bf16x2 %0, %1, %2;" : "=r"(r) : "r"(a), "r"(b));
    return r;
}
__device__ __forceinline__ float bflo(uint32_t v) { return __uint_as_float(v << 16); }
__device__ __forceinline__ float bfhi(uint32_t v) { return __uint_as_float(v & 0xFFFF0000u); }

// ---------------- prep kernels ----------------
__global__ void zero_kernel(int n) {
    int i = blockIdx.x * blockDim.x + threadIdx.x;
    if (i < n) { g_degout[i] = 0; g_degin[i] = 0; }
    if (i == 0) { g_loss = 0.0f; g_done = 0u; }
}

__global__ void count_deg_kernel(const int* __restrict__ src,
                                 const int* __restrict__ dst, int E) {
    int e = blockIdx.x * blockDim.x + threadIdx.x;
    if (e < E) {
        atomicAdd(&g_degout[src[e]], 1);
        atomicAdd(&g_degin[dst[e]], 1);
    }
}

// phase 1: per-block LOCAL exclusive scan of degin, block totals, fused norms
__global__ void scan1_kernel(int n, int npad) {
    __shared__ int wsum[32];
    int t = threadIdx.x, lane = t & 31, w = t >> 5;
    int idx = blockIdx.x * SCAN_BLK + t;
    int v = (idx < n) ? g_degin[idx] : 0;
    int x = v;
    #pragma unroll
    for (int o = 1; o < 32; o <<= 1) {
        int y = __shfl_up_sync(0xffffffffu, x, o);
        if (lane >= o) x += y;
    }
    if (lane == 31) wsum[w] = x;
    __syncthreads();
    if (w == 0) {
        int s = wsum[lane];
        #pragma unroll
        for (int o = 1; o < 32; o <<= 1) {
            int y = __shfl_up_sync(0xffffffffu, s, o);
            if (lane >= o) s += y;
        }
        wsum[lane] = s;
    }
    __syncthreads();
    int woff = (w > 0) ? wsum[w - 1] : 0;
    if (idx < n) {
        int loc = woff + x - v;
        g_rowptr[idx] = loc;
        g_cursor[idx] = loc;
    }
    if (t == 0) g_bsum[blockIdx.x] = wsum[31];
    if (idx < n) {
        int od = g_degout[idx]; if (od < 1) od = 1;
        int id = v;             if (id < 1) id = 1;
        g_nsrc[idx] = rsqrtf((float)od);
        g_ndst[idx] = rsqrtf((float)id);
    } else if (idx < npad) {
        g_nsrc[idx] = 0.0f;   // pad rows produce clean zeros
    }
}

// per-block recompute of the <=64-entry exclusive block-offset prefix
__device__ __forceinline__ void load_boff(int* sboff, int nb, int tid) {
    if (tid < NBLK_MAX) {
        int s = 0;
        for (int i = 0; i < tid && i < nb; i++) s += g_bsum[i];
        sboff[tid] = s;
    }
    __syncthreads();
}

__global__ void fill_kernel(const int* __restrict__ src,
                            const int* __restrict__ dst, int E, int nb) {
    __shared__ int sboff[NBLK_MAX];
    load_boff(sboff, nb, threadIdx.x);
    int e = blockIdx.x * blockDim.x + threadIdx.x;
    if (e < E) {
        int d = dst[e];
        int p = atomicAdd(&g_cursor[d], 1) + sboff[d >> 10];
        g_esrc[p] = src[e];
    }
}

// fp32 -> bf16 weights: layers 0..2 from Ws, slot 3 from dec_W
__global__ void convw_kernel(const float* __restrict__ Ws, const float* __restrict__ dW) {
    int i = blockIdx.x * blockDim.x + threadIdx.x;
    const int n3 = 3 * TILE_ELEMS / 2;
    if (i < n3) {
        float2 v = ((const float2*)Ws)[i];
        ((uint32_t*)g_Wb)[i] = bf16x2(v.x, v.y);
    } else if (i < n3 + TILE_ELEMS / 2) {
        float2 v = ((const float2*)dW)[i - n3];
        ((uint32_t*)g_Wb)[i] = bf16x2(v.x, v.y);
    }
}

// attr fp32 -> bf16 (pad rows zeroed); one warp per row
__global__ void copy_attr_kernel(const float* __restrict__ attr, int n, int npad) {
    int node = (blockIdx.x * blockDim.x + threadIdx.x) >> 5;
    int lane = threadIdx.x & 31;
    if (node >= npad) return;
    float4 v = make_float4(0.f, 0.f, 0.f, 0.f);
    if (node < n) v = ((const float4*)(attr + (size_t)node * HID))[lane];
    ((uint2*)(g_hB + (size_t)node * HID))[lane] =
        make_uint2(bf16x2(v.x, v.y), bf16x2(v.z, v.w));
}

__global__ void mask_kernel(const int* __restrict__ mask_nodes,
                            const float* __restrict__ token, int nmask) {
    int w = (blockIdx.x * blockDim.x + threadIdx.x) >> 5;
    int lane = threadIdx.x & 31;
    if (w >= nmask) return;
    int node = mask_nodes[w];
    float4 v = ((const float4*)token)[lane];
    ((uint2*)(g_hB + (size_t)node * HID))[lane] =
        make_uint2(bf16x2(v.x, v.y), bf16x2(v.z, v.w));
}

// ---------------- bf16 HMMA GEMM: hs[tile] = (h_tile @ W) * nsrc ----------------
__global__ __launch_bounds__(256) void gemm_mma_kernel(const __nv_bfloat16* __restrict__ Wb) {
    extern __shared__ __nv_bfloat16 sm[];
    __nv_bfloat16* sA = sm;                 // 128 x ASTRIDE
    __nv_bfloat16* sB = sm + 128 * ASTRIDE;
    int tid = threadIdx.x, lane = tid & 31, wid = tid >> 5;

    {
        int row = tid >> 1, half = tid & 1;
        const uint4* ga = (const uint4*)(g_hB + (size_t)blockIdx.x * 128 * HID
                                         + row * HID + half * 64);
        const uint4* gb = (const uint4*)(Wb + row * HID + half * 64);
        uint4* pa = (uint4*)(sA + row * ASTRIDE + half * 64);
        uint4* pb = (uint4*)(sB + row * ASTRIDE + half * 64);
        #pragma unroll
        for (int i = 0; i < 8; i++) { pa[i] = ga[i]; pb[i] = gb[i]; }
    }
    __syncthreads();

    uint32_t aaddr = smem_u32(sA)
        + (uint32_t)(((wid * 16) + ((lane >> 3) & 1) * 8 + (lane & 7)) * ASTRIDE
                     + ((lane >> 4) * 8)) * 2;
    uint32_t baddr = smem_u32(sB) + (uint32_t)((lane & 15) * ASTRIDE) * 2;

    float acc[16][4];
    #pragma unroll
    for (int j = 0; j < 16; j++)
        #pragma unroll
        for (int q = 0; q < 4; q++) acc[j][q] = 0.f;

    #pragma unroll
    for (int ks = 0; ks < 8; ks++) {
        uint32_t a0, a1, a2, a3;
        asm volatile("ldmatrix.sync.aligned.m8n8.x4.shared.b16 {%0,%1,%2,%3}, [%4];"
            : "=r"(a0), "=r"(a1), "=r"(a2), "=r"(a3) : "r"(aaddr + ks * 32));
        #pragma unroll
        for (int j = 0; j < 16; j++) {
            uint32_t b0, b1;
            asm volatile("ldmatrix.sync.aligned.m8n8.x2.trans.shared.b16 {%0,%1}, [%2];"
                : "=r"(b0), "=r"(b1)
                : "r"(baddr + (uint32_t)(ks * 16 * ASTRIDE + j * 8) * 2));
            asm volatile(
                "mma.sync.aligned.m16n8k16.row.col.f32.bf16.bf16.f32 "
                "{%0,%1,%2,%3}, {%4,%5,%6,%7}, {%8,%9}, {%0,%1,%2,%3};"
                : "+f"(acc[j][0]), "+f"(acc[j][1]), "+f"(acc[j][2]), "+f"(acc[j][3])
                : "r"(a0), "r"(a1), "r"(a2), "r"(a3), "r"(b0), "r"(b1));
        }
    }

    int r0 = blockIdx.x * 128 + wid * 16 + (lane >> 2);
    int r1 = r0 + 8;
    float s0 = g_nsrc[r0], s1 = g_nsrc[r1];
    uint32_t* o0 = (uint32_t*)(g_hs + (size_t)r0 * HID) + (lane & 3);
    uint32_t* o1 = (uint32_t*)(g_hs + (size_t)r1 * HID) + (lane & 3);
    #pragma unroll
    for (int j = 0; j < 16; j++) {
        o0[j * 4] = bf16x2(acc[j][0] * s0, acc[j][1] * s0);
        o1[j * 4] = bf16x2(acc[j][2] * s1, acc[j][3] * s1);
    }
}

// ------- CSR aggregation: bf16x2 packed accumulate, fp32 epilogue -------
__global__ void aggregate_kernel(const float* __restrict__ bias, int n, int E, int nb) {
    __shared__ int sboff[NBLK_MAX];
    load_boff(sboff, nb, threadIdx.x);
    int w = (blockIdx.x * blockDim.x + threadIdx.x) >> 5;
    int lane = threadIdx.x & 31;
    if (w >= n) return;
    int beg = g_rowptr[w] + sboff[w >> 10];
    int end = (w == n - 1) ? E : g_rowptr[w + 1] + sboff[(w + 1) >> 10];
    const char* hs = (const char*)g_hs;
    int loff = lane << 3;
    // two independent packed accumulator pairs to widen MLP
    uint32_t p01a = 0u, p23a = 0u, p01b = 0u, p23b = 0u;
    int i = beg;
    for (; i + 2 <= end; i += 2) {
        int s0 = g_esrc[i], s1 = g_esrc[i + 1];
        uint2 v0 = *(const uint2*)(hs + ((size_t)s0 << 8) + loff);
        uint2 v1 = *(const uint2*)(hs + ((size_t)s1 << 8) + loff);
        p01a = hadd2bf(p01a, v0.x); p23a = hadd2bf(p23a, v0.y);
        p01b = hadd2bf(p01b, v1.x); p23b = hadd2bf(p23b, v1.y);
    }
    if (i < end) {
        int s0 = g_esrc[i];
        uint2 v0 = *(const uint2*)(hs + ((size_t)s0 << 8) + loff);
        p01a = hadd2bf(p01a, v0.x); p23a = hadd2bf(p23a, v0.y);
    }
    float ax = bflo(p01a) + bflo(p01b);
    float ay = bfhi(p01a) + bfhi(p01b);
    float az = bflo(p23a) + bflo(p23b);
    float aw = bfhi(p23a) + bfhi(p23b);
    float nd = g_ndst[w];
    float4 b = __ldg((const float4*)bias + lane);
    float4 o;
    o.x = fmaxf(ax * nd + b.x, 0.f);
    o.y = fmaxf(ay * nd + b.y, 0.f);
    o.z = fmaxf(az * nd + b.z, 0.f);
    o.w = fmaxf(aw * nd + b.w, 0.f);
    ((uint2*)(g_hB + (size_t)w * HID))[lane] =
        make_uint2(bf16x2(o.x, o.y), bf16x2(o.z, o.w));
}

// ---------------- HMMA decoder (128 masked rows/block) + fused MSE + finalize ------
__global__ __launch_bounds__(256) void decode_mma_kernel(
    const __nv_bfloat16* __restrict__ WdB, const float* __restrict__ db,
    const float* __restrict__ attr, const int* __restrict__ mask_nodes,
    int nmask, float* __restrict__ out, int nblocks) {
    extern __shared__ __nv_bfloat16 sm[];
    __nv_bfloat16* sA = sm;
    __nv_bfloat16* sB = sm + 128 * ASTRIDE;
    __shared__ int rows[128];
    __shared__ float wpart[8];
    int tid = threadIdx.x, lane = tid & 31, wid = tid >> 5;

    int m0 = blockIdx.x * 128;
    if (tid < 128) {
        int mi = m0 + tid;
        rows[tid] = (mi < nmask) ? mask_nodes[mi] : -1;
    }
    __syncthreads();

    {
        int row = tid >> 1, half = tid & 1;
        int node = rows[row];
        uint4* pa = (uint4*)(sA + row * ASTRIDE + half * 64);
        const uint4* gb = (const uint4*)(WdB + row * HID + half * 64);
        uint4* pb = (uint4*)(sB + row * ASTRIDE + half * 64);
        if (node >= 0) {
            const uint4* ga = (const uint4*)(g_hB + (size_t)node * HID + half * 64);
            #pragma unroll
            for (int i = 0; i < 8; i++) { pa[i] = ga[i]; pb[i] = gb[i]; }
        } else {
            uint4 z = make_uint4(0, 0, 0, 0);
            #pragma unroll
            for (int i = 0; i < 8; i++) { pa[i] = z; pb[i] = gb[i]; }
        }
    }
    __syncthreads();

    uint32_t aaddr = smem_u32(sA)
        + (uint32_t)(((wid * 16) + ((lane >> 3) & 1) * 8 + (lane & 7)) * ASTRIDE
                     + ((lane >> 4) * 8)) * 2;
    uint32_t baddr = smem_u32(sB) + (uint32_t)((lane & 15) * ASTRIDE) * 2;

    float acc[16][4];
    #pragma unroll
    for (int j = 0; j < 16; j++)
        #pragma unroll
        for (int q = 0; q < 4; q++) acc[j][q] = 0.f;

    #pragma unroll
    for (int ks = 0; ks < 8; ks++) {
        uint32_t a0, a1, a2, a3;
        asm volatile("ldmatrix.sync.aligned.m8n8.x4.shared.b16 {%0,%1,%2,%3}, [%4];"
            : "=r"(a0), "=r"(a1), "=r"(a2), "=r"(a3) : "r"(aaddr + ks * 32));
        #pragma unroll
        for (int j = 0; j < 16; j++) {
            uint32_t b0, b1;
            asm volatile("ldmatrix.sync.aligned.m8n8.x2.trans.shared.b16 {%0,%1}, [%2];"
                : "=r"(b0), "=r"(b1)
                : "r"(baddr + (uint32_t)(ks * 16 * ASTRIDE + j * 8) * 2));
            asm volatile(
                "mma.sync.aligned.m16n8k16.row.col.f32.bf16.bf16.f32 "
                "{%0,%1,%2,%3}, {%4,%5,%6,%7}, {%8,%9}, {%0,%1,%2,%3};"
                : "+f"(acc[j][0]), "+f"(acc[j][1]), "+f"(acc[j][2]), "+f"(acc[j][3])
                : "r"(a0), "r"(a1), "r"(a2), "r"(a3), "r"(b0), "r"(b1));
        }
    }

    int rl0 = wid * 16 + (lane >> 2);
    int rl1 = rl0 + 8;
    int node0 = rows[rl0], node1 = rows[rl1];
    float sse = 0.f;
    #pragma unroll
    for (int j = 0; j < 16; j++) {
        int c = j * 8 + (lane & 3) * 2;
        float2 dbv = __ldg((const float2*)(db + c));
        if (node0 >= 0) {
            float2 a = __ldg((const float2*)(attr + (size_t)node0 * HID + c));
            float d0 = acc[j][0] + dbv.x - a.x;
            float d1 = acc[j][1] + dbv.y - a.y;
            sse += d0 * d0 + d1 * d1;
        }
        if (node1 >= 0) {
            float2 a = __ldg((const float2*)(attr + (size_t)node1 * HID + c));
            float d2 = acc[j][2] + dbv.x - a.x;
            float d3 = acc[j][3] + dbv.y - a.y;
            sse += d2 * d2 + d3 * d3;
        }
    }
    #pragma unroll
    for (int o = 16; o > 0; o >>= 1)
        sse += __shfl_down_sync(0xffffffffu, sse, o);
    if (lane == 0) wpart[wid] = sse;
    __syncthreads();
    if (tid == 0) {
        float t = 0.f;
        #pragma unroll
        for (int i = 0; i < 8; i++) t += wpart[i];
        atomicAdd(&g_loss, t);
        __threadfence();
        unsigned int done = atomicAdd(&g_done, 1u);
        if (done == (unsigned int)(nblocks - 1)) {
            out[0] = g_loss / (float)((size_t)nmask * HID);
        }
    }
}

// ---------------- host launcher (fork-join streams inside capture) ----------------
extern "C" void kernel_launch(void* const* d_in, const int* in_sizes, int n_in,
                              void* d_out, int out_size) {
    const float* attr       = (const float*)d_in[0];
    const int*   src        = (const int*)d_in[1];
    const int*   dst        = (const int*)d_in[2];
    const float* Ws         = (const float*)d_in[3];
    const float* bs         = (const float*)d_in[4];
    const float* dec_W      = (const float*)d_in[5];
    const float* dec_b      = (const float*)d_in[6];
    const float* mask_token = (const float*)d_in[7];
    const int*   mask_nodes = (const int*)d_in[8];

    int N      = in_sizes[0] / HID;
    int E      = in_sizes[1];
    int nmask  = in_sizes[8];
    int npad   = (N + 127) & ~127;
    int ntiles = npad / 128;
    int nb     = (N + SCAN_BLK - 1) / SCAN_BLK;
    int ndec   = (nmask + 127) / 128;

    __nv_bfloat16* Wb = nullptr;
    cudaGetSymbolAddress((void**)&Wb, g_Wb);

    const int smem_gemm = 2 * 128 * ASTRIDE * 2;   // 69632 B
    static bool init = false;
    static cudaStream_t sB, sC;
    static cudaEvent_t eFork, eS1, eC, eB, eG0;
    if (!init) {
        cudaFuncSetAttribute(gemm_mma_kernel,
                             cudaFuncAttributeMaxDynamicSharedMemorySize, smem_gemm);
        cudaFuncSetAttribute(decode_mma_kernel,
                             cudaFuncAttributeMaxDynamicSharedMemorySize, smem_gemm);
        cudaStreamCreateWithFlags(&sB, cudaStreamNonBlocking);
        cudaStreamCreateWithFlags(&sC, cudaStreamNonBlocking);
        cudaEventCreateWithFlags(&eFork, cudaEventDisableTiming);
        cudaEventCreateWithFlags(&eS1, cudaEventDisableTiming);
        cudaEventCreateWithFlags(&eC, cudaEventDisableTiming);
        cudaEventCreateWithFlags(&eB, cudaEventDisableTiming);
        cudaEventCreateWithFlags(&eG0, cudaEventDisableTiming);
        init = true;
    }

    // fork
    cudaEventRecord(eFork, 0);
    cudaStreamWaitEvent(sB, eFork, 0);
    cudaStreamWaitEvent(sC, eFork, 0);

    // chain A (default stream): degrees -> scan -> fill
    zero_kernel<<<(N + 255) / 256, 256>>>(N);
    count_deg_kernel<<<(E + 255) / 256, 256>>>(src, dst, E);
    scan1_kernel<<<nb, SCAN_BLK>>>(N, npad);
    cudaEventRecord(eS1, 0);
    fill_kernel<<<(E + 255) / 256, 256>>>(src, dst, E, nb);

    // chain B: weights, then layer-0 GEMM (needs Wb + hB + nsrc)
    convw_kernel<<<(4 * TILE_ELEMS / 2 + 255) / 256, 256, 0, sB>>>(Ws, dec_W);
    // chain C: features
    copy_attr_kernel<<<(npad * 32 + 255) / 256, 256, 0, sC>>>(attr, N, npad);
    mask_kernel<<<(nmask * 32 + 255) / 256, 256, 0, sC>>>(mask_nodes, mask_token, nmask);
    cudaEventRecord(eC, sC);

    cudaStreamWaitEvent(sB, eS1, 0);
    cudaStreamWaitEvent(sB, eC, 0);
    gemm_mma_kernel<<<ntiles, 256, smem_gemm, sB>>>(Wb);   // layer 0, overlaps fill
    cudaEventRecord(eG0, sB);

    // join on default stream
    cudaStreamWaitEvent(0, eG0, 0);
    aggregate_kernel<<<(N * 32 + 255) / 256, 256>>>(bs, N, E, nb);

    for (int l = 1; l < 3; l++) {
        gemm_mma_kernel<<<ntiles, 256, smem_gemm>>>(Wb + (size_t)l * TILE_ELEMS);
        aggregate_kernel<<<(N * 32 + 255) / 256, 256>>>(bs + (size_t)l * HID, N, E, nb);
    }

    decode_mma_kernel<<<ndec, 256, smem_gemm>>>(
        Wb + 3 * (size_t)TILE_ELEMS, dec_b, attr, mask_nodes, nmask,
        (float*)d_out, ndec);
}